// round 2
// baseline (speedup 1.0000x reference)
#include <cuda_runtime.h>
#include <math.h>

#define NB    2
#define SEQ   2048
#define HID   2048
#define NHEAD 16
#define HD    128
#define NBH   (NB*NHEAD)     // 32
#define MTOK  (NB*SEQ)       // 4096
#define QKVN  (3*HID)        // 6144
#define NEG_BIG (-1e30f)
#define SM_SCALE 0.08838834764831845f   // 1/sqrt(128)

// Scratch (static __device__ arrays: the allocation-guard-safe workaround)
static __device__ float g_qkv   [(size_t)MTOK * QKVN];        // ~100.7 MB, [b,s,{q,k,v},h,d]
static __device__ float g_scores[(size_t)NBH * SEQ * SEQ];    // ~536.9 MB
static __device__ float g_attn  [(size_t)MTOK * HID];         // ~33.6 MB, [b,s,h*hd+d]

// ---------------------------------------------------------------------------
// 128x128 tile GEMM cores: 256 threads, 8x8 per thread (split-4 mapping),
// BK=8, float4 global loads, conflict-free float4 shared reads.
// ---------------------------------------------------------------------------

// NT: C[128,128] += A0[128,K] * B0[128,K]^T   (both K-contiguous, strides lda/ldb)
__device__ __forceinline__ void nt_core(const float* __restrict__ A0,
                                        const float* __restrict__ B0,
                                        size_t lda, size_t ldb, int K,
                                        float (&acc)[8][8])
{
    __shared__ float As[8][128];
    __shared__ float Bs[8][128];
    const int tid  = threadIdx.x;
    const int tx   = tid & 15, ty = tid >> 4;
    const int lrow = tid >> 1;
    const int lcol = (tid & 1) * 4;
    const float* Ap = A0 + (size_t)lrow * lda + lcol;
    const float* Bp = B0 + (size_t)lrow * ldb + lcol;
    for (int k0 = 0; k0 < K; k0 += 8) {
        float4 a4 = *(const float4*)(Ap + k0);
        float4 b4 = *(const float4*)(Bp + k0);
        As[lcol+0][lrow] = a4.x; As[lcol+1][lrow] = a4.y;
        As[lcol+2][lrow] = a4.z; As[lcol+3][lrow] = a4.w;
        Bs[lcol+0][lrow] = b4.x; Bs[lcol+1][lrow] = b4.y;
        Bs[lcol+2][lrow] = b4.z; Bs[lcol+3][lrow] = b4.w;
        __syncthreads();
        #pragma unroll
        for (int k = 0; k < 8; k++) {
            float4 a0 = *(const float4*)&As[k][ty*4];
            float4 a1 = *(const float4*)&As[k][64 + ty*4];
            float4 b0 = *(const float4*)&Bs[k][tx*4];
            float4 b1 = *(const float4*)&Bs[k][64 + tx*4];
            float ra[8] = {a0.x,a0.y,a0.z,a0.w,a1.x,a1.y,a1.z,a1.w};
            float rb[8] = {b0.x,b0.y,b0.z,b0.w,b1.x,b1.y,b1.z,b1.w};
            #pragma unroll
            for (int i = 0; i < 8; i++)
                #pragma unroll
                for (int j = 0; j < 8; j++)
                    acc[i][j] = fmaf(ra[i], rb[j], acc[i][j]);
        }
        __syncthreads();
    }
}

// NN: C[128,128] += A0[128,K] * B0[K,128]   (A K-contiguous stride lda; B rows stride ldb)
__device__ __forceinline__ void nn_core(const float* __restrict__ A0,
                                        const float* __restrict__ B0,
                                        size_t lda, size_t ldb, int K,
                                        float (&acc)[8][8])
{
    __shared__ float As[8][128];
    __shared__ float Bs[8][128];
    const int tid  = threadIdx.x;
    const int tx   = tid & 15, ty = tid >> 4;
    const int lrow = tid >> 1;
    const int lcol = (tid & 1) * 4;
    const int brow = tid >> 5;          // 0..7
    const int bcol = (tid & 31) * 4;    // 0..124
    const float* Ap = A0 + (size_t)lrow * lda + lcol;
    for (int k0 = 0; k0 < K; k0 += 8) {
        float4 a4 = *(const float4*)(Ap + k0);
        float4 b4 = *(const float4*)(B0 + (size_t)(k0 + brow) * ldb + bcol);
        As[lcol+0][lrow] = a4.x; As[lcol+1][lrow] = a4.y;
        As[lcol+2][lrow] = a4.z; As[lcol+3][lrow] = a4.w;
        *(float4*)&Bs[brow][bcol] = b4;
        __syncthreads();
        #pragma unroll
        for (int k = 0; k < 8; k++) {
            float4 a0 = *(const float4*)&As[k][ty*4];
            float4 a1 = *(const float4*)&As[k][64 + ty*4];
            float4 b0 = *(const float4*)&Bs[k][tx*4];
            float4 b1 = *(const float4*)&Bs[k][64 + tx*4];
            float ra[8] = {a0.x,a0.y,a0.z,a0.w,a1.x,a1.y,a1.z,a1.w};
            float rb[8] = {b0.x,b0.y,b0.z,b0.w,b1.x,b1.y,b1.z,b1.w};
            #pragma unroll
            for (int i = 0; i < 8; i++)
                #pragma unroll
                for (int j = 0; j < 8; j++)
                    acc[i][j] = fmaf(ra[i], rb[j], acc[i][j]);
        }
        __syncthreads();
    }
}

// ---------------------------------------------------------------------------
// 1) QKV projection: g_qkv[m, n] = x[m,:] . qkv_w[n,:] + qkv_b[n]
// ---------------------------------------------------------------------------
__global__ __launch_bounds__(256)
void gemm_qkv(const float* __restrict__ x, const float* __restrict__ w,
              const float* __restrict__ bias)
{
    const int bm = blockIdx.y * 128;
    const int bn = blockIdx.x * 128;
    float acc[8][8] = {};
    nt_core(x + (size_t)bm * HID, w + (size_t)bn * HID, HID, HID, HID, acc);
    const int tx = threadIdx.x & 15, ty = threadIdx.x >> 4;
    #pragma unroll
    for (int ih = 0; ih < 2; ih++)
    #pragma unroll
    for (int ii = 0; ii < 4; ii++) {
        int row = bm + ih*64 + ty*4 + ii;
        #pragma unroll
        for (int jh = 0; jh < 2; jh++) {
            int col = bn + jh*64 + tx*4;
            float4 v;
            v.x = acc[ih*4+ii][jh*4+0] + bias[col+0];
            v.y = acc[ih*4+ii][jh*4+1] + bias[col+1];
            v.z = acc[ih*4+ii][jh*4+2] + bias[col+2];
            v.w = acc[ih*4+ii][jh*4+3] + bias[col+3];
            *(float4*)(g_qkv + (size_t)row * QKVN + col) = v;
        }
    }
}

// ---------------------------------------------------------------------------
// 2) Interleaved RoPE applied in place to q and k of g_qkv.
//    out[2i]   = x[2i]  *cos(s*f(2i))   - x[2i+1]*sin(s*f(2i))
//    out[2i+1] = x[2i+1]*cos(s*f(2i+1)) + x[2i]  *sin(s*f(2i+1))
//    f(d) = 10000^(-((d mod 64)*2)/128)
// ---------------------------------------------------------------------------
__global__ __launch_bounds__(256)
void rope_kernel()
{
    int idx = blockIdx.x * blockDim.x + threadIdx.x;   // 2*NB*SEQ*NHEAD*64 total
    const int i = idx & 63;  idx >>= 6;
    const int h = idx & 15;  idx >>= 4;
    const int s = idx & (SEQ - 1); idx >>= 11;
    const int b = idx & 1;
    const int which = idx >> 1;                         // 0 = q, 1 = k
    const size_t base = (size_t)(b * SEQ + s) * QKVN + which * HID + h * HD;

    const int j0 = (2*i) & 63;
    const int j1 = (2*i + 1) & 63;
    // 10000^(-j/64) = exp2(-j * log2(10000)/64)
    const float C = 0.20762050593045013f;               // log2(10000)/64
    float f0 = exp2f(-(float)j0 * C);
    float f1 = exp2f(-(float)j1 * C);
    float c0, s0, c1, s1;
    sincosf((float)s * f0, &s0, &c0);
    sincosf((float)s * f1, &s1, &c1);

    float x0 = g_qkv[base + 2*i];
    float x1 = g_qkv[base + 2*i + 1];
    g_qkv[base + 2*i]     = x0 * c0 - x1 * s0;
    g_qkv[base + 2*i + 1] = x1 * c1 + x0 * s1;
}

// ---------------------------------------------------------------------------
// 3) Scores: S[z, m, n] = scale * q[z,m,:].k[z,n,:], causal + key mask fused.
//    Fully-masked (upper-triangular) tiles skip the GEMM entirely.
// ---------------------------------------------------------------------------
__global__ __launch_bounds__(256)
void gemm_scores(const int* __restrict__ amask)
{
    const int z = blockIdx.z;
    const int b = z >> 4;
    const int h = z & 15;
    const int bm = blockIdx.y * 128;
    const int bn = blockIdx.x * 128;
    float* Cz = g_scores + (size_t)z * SEQ * SEQ;
    const int tx = threadIdx.x & 15, ty = threadIdx.x >> 4;

    if (bn > bm + 127) {   // entire tile above the diagonal
        #pragma unroll
        for (int ih = 0; ih < 2; ih++)
        #pragma unroll
        for (int ii = 0; ii < 4; ii++) {
            int row = bm + ih*64 + ty*4 + ii;
            #pragma unroll
            for (int jh = 0; jh < 2; jh++) {
                int col = bn + jh*64 + tx*4;
                float4 v = {NEG_BIG, NEG_BIG, NEG_BIG, NEG_BIG};
                *(float4*)(Cz + (size_t)row * SEQ + col) = v;
            }
        }
        return;
    }

    const float* Qb = g_qkv + (size_t)b * SEQ * QKVN + h * HD;         // q
    const float* Kb = g_qkv + (size_t)b * SEQ * QKVN + HID + h * HD;   // k
    float acc[8][8] = {};
    nt_core(Qb + (size_t)bm * QKVN, Kb + (size_t)bn * QKVN, QKVN, QKVN, HD, acc);

    #pragma unroll
    for (int ih = 0; ih < 2; ih++)
    #pragma unroll
    for (int ii = 0; ii < 4; ii++) {
        int row = bm + ih*64 + ty*4 + ii;
        #pragma unroll
        for (int jh = 0; jh < 2; jh++) {
            int col = bn + jh*64 + tx*4;
            float4 v;
            float* pv = &v.x;
            #pragma unroll
            for (int jj = 0; jj < 4; jj++) {
                float val = acc[ih*4+ii][jh*4+jj] * SM_SCALE;
                int c = col + jj;
                if (c > row || amask[b * SEQ + c] == 0) val = NEG_BIG;
                pv[jj] = val;
            }
            *(float4*)(Cz + (size_t)row * SEQ + col) = v;
        }
    }
}

// ---------------------------------------------------------------------------
// 4) Row softmax over g_scores (one 256-thread block per row of 2048).
// ---------------------------------------------------------------------------
__global__ __launch_bounds__(256)
void softmax_rows()
{
    float* p = g_scores + (size_t)blockIdx.x * SEQ;
    const int tid = threadIdx.x;
    __shared__ float red[256];

    float v[8];
    float4 u0 = *(const float4*)(p + tid*8);
    float4 u1 = *(const float4*)(p + tid*8 + 4);
    v[0]=u0.x; v[1]=u0.y; v[2]=u0.z; v[3]=u0.w;
    v[4]=u1.x; v[5]=u1.y; v[6]=u1.z; v[7]=u1.w;

    float mx = NEG_BIG;
    #pragma unroll
    for (int i = 0; i < 8; i++) mx = fmaxf(mx, v[i]);
    red[tid] = mx; __syncthreads();
    for (int off = 128; off > 0; off >>= 1) {
        if (tid < off) red[tid] = fmaxf(red[tid], red[tid + off]);
        __syncthreads();
    }
    mx = red[0]; __syncthreads();

    float sum = 0.f;
    #pragma unroll
    for (int i = 0; i < 8; i++) { v[i] = expf(v[i] - mx); sum += v[i]; }
    red[tid] = sum; __syncthreads();
    for (int off = 128; off > 0; off >>= 1) {
        if (tid < off) red[tid] += red[tid + off];
        __syncthreads();
    }
    float inv = 1.0f / red[0];

    float4 w0, w1;
    w0.x=v[0]*inv; w0.y=v[1]*inv; w0.z=v[2]*inv; w0.w=v[3]*inv;
    w1.x=v[4]*inv; w1.y=v[5]*inv; w1.z=v[6]*inv; w1.w=v[7]*inv;
    *(float4*)(p + tid*8)     = w0;
    *(float4*)(p + tid*8 + 4) = w1;
}

// ---------------------------------------------------------------------------
// 5) attn = P @ V, K-loop truncated at causal bound; writes [b, s, h*hd + d].
// ---------------------------------------------------------------------------
__global__ __launch_bounds__(256)
void gemm_pv()
{
    const int z = blockIdx.y;
    const int b = z >> 4;
    const int h = z & 15;
    const int bm = blockIdx.x * 128;
    const float* P = g_scores + (size_t)z * SEQ * SEQ;
    const float* V = g_qkv + (size_t)b * SEQ * QKVN + 2*HID + h * HD;
    float* C = g_attn + (size_t)b * SEQ * HID + h * HD;

    const int kend = bm + 128;   // P is zero beyond the causal bound
    float acc[8][8] = {};
    nn_core(P + (size_t)bm * SEQ, V, SEQ, QKVN, kend, acc);

    const int tx = threadIdx.x & 15, ty = threadIdx.x >> 4;
    #pragma unroll
    for (int ih = 0; ih < 2; ih++)
    #pragma unroll
    for (int ii = 0; ii < 4; ii++) {
        int row = bm + ih*64 + ty*4 + ii;
        #pragma unroll
        for (int jh = 0; jh < 2; jh++) {
            int col = jh*64 + tx*4;
            float4 v;
            v.x = acc[ih*4+ii][jh*4+0];
            v.y = acc[ih*4+ii][jh*4+1];
            v.z = acc[ih*4+ii][jh*4+2];
            v.w = acc[ih*4+ii][jh*4+3];
            *(float4*)(C + (size_t)row * HID + col) = v;
        }
    }
}

// ---------------------------------------------------------------------------
// 6) Output projection: out = g_attn @ out_w^T + out_b
// ---------------------------------------------------------------------------
__global__ __launch_bounds__(256)
void gemm_out(const float* __restrict__ w, const float* __restrict__ bias,
              float* __restrict__ outp)
{
    const int bm = blockIdx.y * 128;
    const int bn = blockIdx.x * 128;
    float acc[8][8] = {};
    nt_core(g_attn + (size_t)bm * HID, w + (size_t)bn * HID, HID, HID, HID, acc);
    const int tx = threadIdx.x & 15, ty = threadIdx.x >> 4;
    #pragma unroll
    for (int ih = 0; ih < 2; ih++)
    #pragma unroll
    for (int ii = 0; ii < 4; ii++) {
        int row = bm + ih*64 + ty*4 + ii;
        #pragma unroll
        for (int jh = 0; jh < 2; jh++) {
            int col = bn + jh*64 + tx*4;
            float4 v;
            v.x = acc[ih*4+ii][jh*4+0] + bias[col+0];
            v.y = acc[ih*4+ii][jh*4+1] + bias[col+1];
            v.z = acc[ih*4+ii][jh*4+2] + bias[col+2];
            v.w = acc[ih*4+ii][jh*4+3] + bias[col+3];
            *(float4*)(outp + (size_t)row * HID + col) = v;
        }
    }
}

// ---------------------------------------------------------------------------
extern "C" void kernel_launch(void* const* d_in, const int* in_sizes, int n_in,
                              void* d_out, int out_size)
{
    (void)in_sizes; (void)n_in; (void)out_size;
    const float* x     = (const float*)d_in[0];
    const int*   amask = (const int*)  d_in[1];
    const float* qkv_w = (const float*)d_in[2];
    const float* qkv_b = (const float*)d_in[3];
    const float* out_w = (const float*)d_in[4];
    const float* out_b = (const float*)d_in[5];
    float* outp = (float*)d_out;

    gemm_qkv   <<<dim3(QKVN/128, MTOK/128), 256>>>(x, qkv_w, qkv_b);
    rope_kernel<<<(2*NB*SEQ*NHEAD*64)/256, 256>>>();
    gemm_scores<<<dim3(SEQ/128, SEQ/128, NBH), 256>>>(amask);
    softmax_rows<<<NBH*SEQ, 256>>>();
    gemm_pv    <<<dim3(SEQ/128, NBH), 256>>>();
    gemm_out   <<<dim3(HID/128, MTOK/128), 256>>>(out_w, out_b, outp);
}

// round 5
// speedup vs baseline: 1.0009x; 1.0009x over previous
#include <cuda_runtime.h>
#include <math.h>

#define NB    2
#define SEQ   2048
#define HID   2048
#define NHEAD 16
#define HD    128
#define NBH   (NB*NHEAD)     // 32
#define MTOK  (NB*SEQ)       // 4096
#define QKVN  (3*HID)        // 6144
#define NEG_BIG (-1e30f)
#define SM_SCALE 0.08838834764831845f   // 1/sqrt(128)

// Scratch (static __device__ arrays: the allocation-guard-safe workaround)
static __device__ float g_qkv   [(size_t)MTOK * QKVN];        // ~100.7 MB, [b,s,{q,k,v},h,d]
static __device__ float g_scores[(size_t)NBH * SEQ * SEQ];    // ~536.9 MB
static __device__ float g_attn  [(size_t)MTOK * HID];         // ~33.6 MB, [b,s,h*hd+d]

// ---------------------------------------------------------------------------
// 128x128 tile GEMM cores: 256 threads, 8x8 per thread (split-4 mapping),
// BK=8, float4 global loads, conflict-free float4 shared reads.
// ---------------------------------------------------------------------------

// NT: C[128,128] += A0[128,K] * B0[128,K]^T   (both K-contiguous, strides lda/ldb)
__device__ __forceinline__ void nt_core(const float* __restrict__ A0,
                                        const float* __restrict__ B0,
                                        size_t lda, size_t ldb, int K,
                                        float (&acc)[8][8])
{
    __shared__ float As[8][128];
    __shared__ float Bs[8][128];
    const int tid  = threadIdx.x;
    const int tx   = tid & 15, ty = tid >> 4;
    const int lrow = tid >> 1;
    const int lcol = (tid & 1) * 4;
    const float* Ap = A0 + (size_t)lrow * lda + lcol;
    const float* Bp = B0 + (size_t)lrow * ldb + lcol;
    for (int k0 = 0; k0 < K; k0 += 8) {
        float4 a4 = *(const float4*)(Ap + k0);
        float4 b4 = *(const float4*)(Bp + k0);
        As[lcol+0][lrow] = a4.x; As[lcol+1][lrow] = a4.y;
        As[lcol+2][lrow] = a4.z; As[lcol+3][lrow] = a4.w;
        Bs[lcol+0][lrow] = b4.x; Bs[lcol+1][lrow] = b4.y;
        Bs[lcol+2][lrow] = b4.z; Bs[lcol+3][lrow] = b4.w;
        __syncthreads();
        #pragma unroll
        for (int k = 0; k < 8; k++) {
            float4 a0 = *(const float4*)&As[k][ty*4];
            float4 a1 = *(const float4*)&As[k][64 + ty*4];
            float4 b0 = *(const float4*)&Bs[k][tx*4];
            float4 b1 = *(const float4*)&Bs[k][64 + tx*4];
            float ra[8] = {a0.x,a0.y,a0.z,a0.w,a1.x,a1.y,a1.z,a1.w};
            float rb[8] = {b0.x,b0.y,b0.z,b0.w,b1.x,b1.y,b1.z,b1.w};
            #pragma unroll
            for (int i = 0; i < 8; i++)
                #pragma unroll
                for (int j = 0; j < 8; j++)
                    acc[i][j] = fmaf(ra[i], rb[j], acc[i][j]);
        }
        __syncthreads();
    }
}

// NN: C[128,128] += A0[128,K] * B0[K,128]   (A K-contiguous stride lda; B rows stride ldb)
__device__ __forceinline__ void nn_core(const float* __restrict__ A0,
                                        const float* __restrict__ B0,
                                        size_t lda, size_t ldb, int K,
                                        float (&acc)[8][8])
{
    __shared__ float As[8][128];
    __shared__ float Bs[8][128];
    const int tid  = threadIdx.x;
    const int tx   = tid & 15, ty = tid >> 4;
    const int lrow = tid >> 1;
    const int lcol = (tid & 1) * 4;
    const int brow = tid >> 5;          // 0..7
    const int bcol = (tid & 31) * 4;    // 0..124
    const float* Ap = A0 + (size_t)lrow * lda + lcol;
    for (int k0 = 0; k0 < K; k0 += 8) {
        float4 a4 = *(const float4*)(Ap + k0);
        float4 b4 = *(const float4*)(B0 + (size_t)(k0 + brow) * ldb + bcol);
        As[lcol+0][lrow] = a4.x; As[lcol+1][lrow] = a4.y;
        As[lcol+2][lrow] = a4.z; As[lcol+3][lrow] = a4.w;
        *(float4*)&Bs[brow][bcol] = b4;
        __syncthreads();
        #pragma unroll
        for (int k = 0; k < 8; k++) {
            float4 a0 = *(const float4*)&As[k][ty*4];
            float4 a1 = *(const float4*)&As[k][64 + ty*4];
            float4 b0 = *(const float4*)&Bs[k][tx*4];
            float4 b1 = *(const float4*)&Bs[k][64 + tx*4];
            float ra[8] = {a0.x,a0.y,a0.z,a0.w,a1.x,a1.y,a1.z,a1.w};
            float rb[8] = {b0.x,b0.y,b0.z,b0.w,b1.x,b1.y,b1.z,b1.w};
            #pragma unroll
            for (int i = 0; i < 8; i++)
                #pragma unroll
                for (int j = 0; j < 8; j++)
                    acc[i][j] = fmaf(ra[i], rb[j], acc[i][j]);
        }
        __syncthreads();
    }
}

// ---------------------------------------------------------------------------
// 1) QKV projection: g_qkv[m, n] = x[m,:] . qkv_w[n,:] + qkv_b[n]
// ---------------------------------------------------------------------------
__global__ __launch_bounds__(256)
void gemm_qkv(const float* __restrict__ x, const float* __restrict__ w,
              const float* __restrict__ bias)
{
    const int bm = blockIdx.y * 128;
    const int bn = blockIdx.x * 128;
    float acc[8][8] = {};
    nt_core(x + (size_t)bm * HID, w + (size_t)bn * HID, HID, HID, HID, acc);
    const int tx = threadIdx.x & 15, ty = threadIdx.x >> 4;
    #pragma unroll
    for (int ih = 0; ih < 2; ih++)
    #pragma unroll
    for (int ii = 0; ii < 4; ii++) {
        int row = bm + ih*64 + ty*4 + ii;
        #pragma unroll
        for (int jh = 0; jh < 2; jh++) {
            int col = bn + jh*64 + tx*4;
            float4 v;
            v.x = acc[ih*4+ii][jh*4+0] + bias[col+0];
            v.y = acc[ih*4+ii][jh*4+1] + bias[col+1];
            v.z = acc[ih*4+ii][jh*4+2] + bias[col+2];
            v.w = acc[ih*4+ii][jh*4+3] + bias[col+3];
            *(float4*)(g_qkv + (size_t)row * QKVN + col) = v;
        }
    }
}

// ---------------------------------------------------------------------------
// 2) Interleaved RoPE applied in place to q and k of g_qkv.
//    out[2i]   = x[2i]  *cos(s*f(2i))   - x[2i+1]*sin(s*f(2i))
//    out[2i+1] = x[2i+1]*cos(s*f(2i+1)) + x[2i]  *sin(s*f(2i+1))
//    f(d) = 10000^(-((d mod 64)*2)/128)
// ---------------------------------------------------------------------------
__global__ __launch_bounds__(256)
void rope_kernel()
{
    int idx = blockIdx.x * blockDim.x + threadIdx.x;   // 2*NB*SEQ*NHEAD*64 total
    const int i = idx & 63;  idx >>= 6;
    const int h = idx & 15;  idx >>= 4;
    const int s = idx & (SEQ - 1); idx >>= 11;
    const int b = idx & 1;
    const int which = idx >> 1;                         // 0 = q, 1 = k
    const size_t base = (size_t)(b * SEQ + s) * QKVN + which * HID + h * HD;

    const int j0 = (2*i) & 63;
    const int j1 = (2*i + 1) & 63;
    // 10000^(-j/64) = exp2(-j * log2(10000)/64)
    const float C = 0.20762050593045013f;               // log2(10000)/64
    float f0 = exp2f(-(float)j0 * C);
    float f1 = exp2f(-(float)j1 * C);
    float c0, s0, c1, s1;
    sincosf((float)s * f0, &s0, &c0);
    sincosf((float)s * f1, &s1, &c1);

    float x0 = g_qkv[base + 2*i];
    float x1 = g_qkv[base + 2*i + 1];
    g_qkv[base + 2*i]     = x0 * c0 - x1 * s0;
    g_qkv[base + 2*i + 1] = x1 * c1 + x0 * s1;
}

// ---------------------------------------------------------------------------
// 3) Scores: S[z, m, n] = scale * q[z,m,:].k[z,n,:], causal + key mask fused.
//    Fully-masked (upper-triangular) tiles skip the GEMM entirely.
// ---------------------------------------------------------------------------
__global__ __launch_bounds__(256)
void gemm_scores(const int* __restrict__ amask)
{
    const int z = blockIdx.z;
    const int b = z >> 4;
    const int h = z & 15;
    const int bm = blockIdx.y * 128;
    const int bn = blockIdx.x * 128;
    float* Cz = g_scores + (size_t)z * SEQ * SEQ;
    const int tx = threadIdx.x & 15, ty = threadIdx.x >> 4;

    if (bn > bm + 127) {   // entire tile above the diagonal
        #pragma unroll
        for (int ih = 0; ih < 2; ih++)
        #pragma unroll
        for (int ii = 0; ii < 4; ii++) {
            int row = bm + ih*64 + ty*4 + ii;
            #pragma unroll
            for (int jh = 0; jh < 2; jh++) {
                int col = bn + jh*64 + tx*4;
                float4 v = {NEG_BIG, NEG_BIG, NEG_BIG, NEG_BIG};
                *(float4*)(Cz + (size_t)row * SEQ + col) = v;
            }
        }
        return;
    }

    const float* Qb = g_qkv + (size_t)b * SEQ * QKVN + h * HD;         // q
    const float* Kb = g_qkv + (size_t)b * SEQ * QKVN + HID + h * HD;   // k
    float acc[8][8] = {};
    nt_core(Qb + (size_t)bm * QKVN, Kb + (size_t)bn * QKVN, QKVN, QKVN, HD, acc);

    #pragma unroll
    for (int ih = 0; ih < 2; ih++)
    #pragma unroll
    for (int ii = 0; ii < 4; ii++) {
        int row = bm + ih*64 + ty*4 + ii;
        #pragma unroll
        for (int jh = 0; jh < 2; jh++) {
            int col = bn + jh*64 + tx*4;
            float4 v;
            float* pv = &v.x;
            #pragma unroll
            for (int jj = 0; jj < 4; jj++) {
                float val = acc[ih*4+ii][jh*4+jj] * SM_SCALE;
                int c = col + jj;
                if (c > row || amask[b * SEQ + c] == 0) val = NEG_BIG;
                pv[jj] = val;
            }
            *(float4*)(Cz + (size_t)row * SEQ + col) = v;
        }
    }
}

// ---------------------------------------------------------------------------
// 4) Row softmax over g_scores (one 256-thread block per row of 2048).
// ---------------------------------------------------------------------------
__global__ __launch_bounds__(256)
void softmax_rows()
{
    float* p = g_scores + (size_t)blockIdx.x * SEQ;
    const int tid = threadIdx.x;
    __shared__ float red[256];

    float v[8];
    float4 u0 = *(const float4*)(p + tid*8);
    float4 u1 = *(const float4*)(p + tid*8 + 4);
    v[0]=u0.x; v[1]=u0.y; v[2]=u0.z; v[3]=u0.w;
    v[4]=u1.x; v[5]=u1.y; v[6]=u1.z; v[7]=u1.w;

    float mx = NEG_BIG;
    #pragma unroll
    for (int i = 0; i < 8; i++) mx = fmaxf(mx, v[i]);
    red[tid] = mx; __syncthreads();
    for (int off = 128; off > 0; off >>= 1) {
        if (tid < off) red[tid] = fmaxf(red[tid], red[tid + off]);
        __syncthreads();
    }
    mx = red[0]; __syncthreads();

    float sum = 0.f;
    #pragma unroll
    for (int i = 0; i < 8; i++) { v[i] = expf(v[i] - mx); sum += v[i]; }
    red[tid] = sum; __syncthreads();
    for (int off = 128; off > 0; off >>= 1) {
        if (tid < off) red[tid] += red[tid + off];
        __syncthreads();
    }
    float inv = 1.0f / red[0];

    float4 w0, w1;
    w0.x=v[0]*inv; w0.y=v[1]*inv; w0.z=v[2]*inv; w0.w=v[3]*inv;
    w1.x=v[4]*inv; w1.y=v[5]*inv; w1.z=v[6]*inv; w1.w=v[7]*inv;
    *(float4*)(p + tid*8)     = w0;
    *(float4*)(p + tid*8 + 4) = w1;
}

// ---------------------------------------------------------------------------
// 5) attn = P @ V, K-loop truncated at causal bound; writes [b, s, h*hd + d].
// ---------------------------------------------------------------------------
__global__ __launch_bounds__(256)
void gemm_pv()
{
    const int z = blockIdx.y;
    const int b = z >> 4;
    const int h = z & 15;
    const int bm = blockIdx.x * 128;
    const float* P = g_scores + (size_t)z * SEQ * SEQ;
    const float* V = g_qkv + (size_t)b * SEQ * QKVN + 2*HID + h * HD;
    float* C = g_attn + (size_t)b * SEQ * HID + h * HD;

    const int kend = bm + 128;   // P is zero beyond the causal bound
    float acc[8][8] = {};
    nn_core(P + (size_t)bm * SEQ, V, SEQ, QKVN, kend, acc);

    const int tx = threadIdx.x & 15, ty = threadIdx.x >> 4;
    #pragma unroll
    for (int ih = 0; ih < 2; ih++)
    #pragma unroll
    for (int ii = 0; ii < 4; ii++) {
        int row = bm + ih*64 + ty*4 + ii;
        #pragma unroll
        for (int jh = 0; jh < 2; jh++) {
            int col = jh*64 + tx*4;
            float4 v;
            v.x = acc[ih*4+ii][jh*4+0];
            v.y = acc[ih*4+ii][jh*4+1];
            v.z = acc[ih*4+ii][jh*4+2];
            v.w = acc[ih*4+ii][jh*4+3];
            *(float4*)(C + (size_t)row * HID + col) = v;
        }
    }
}

// ---------------------------------------------------------------------------
// 6) Output projection: out = g_attn @ out_w^T + out_b
// ---------------------------------------------------------------------------
__global__ __launch_bounds__(256)
void gemm_out(const float* __restrict__ w, const float* __restrict__ bias,
              float* __restrict__ outp)
{
    const int bm = blockIdx.y * 128;
    const int bn = blockIdx.x * 128;
    float acc[8][8] = {};
    nt_core(g_attn + (size_t)bm * HID, w + (size_t)bn * HID, HID, HID, HID, acc);
    const int tx = threadIdx.x & 15, ty = threadIdx.x >> 4;
    #pragma unroll
    for (int ih = 0; ih < 2; ih++)
    #pragma unroll
    for (int ii = 0; ii < 4; ii++) {
        int row = bm + ih*64 + ty*4 + ii;
        #pragma unroll
        for (int jh = 0; jh < 2; jh++) {
            int col = bn + jh*64 + tx*4;
            float4 v;
            v.x = acc[ih*4+ii][jh*4+0] + bias[col+0];
            v.y = acc[ih*4+ii][jh*4+1] + bias[col+1];
            v.z = acc[ih*4+ii][jh*4+2] + bias[col+2];
            v.w = acc[ih*4+ii][jh*4+3] + bias[col+3];
            *(float4*)(outp + (size_t)row * HID + col) = v;
        }
    }
}

// ---------------------------------------------------------------------------
extern "C" void kernel_launch(void* const* d_in, const int* in_sizes, int n_in,
                              void* d_out, int out_size)
{
    (void)in_sizes; (void)n_in; (void)out_size;
    const float* x     = (const float*)d_in[0];
    const int*   amask = (const int*)  d_in[1];
    const float* qkv_w = (const float*)d_in[2];
    const float* qkv_b = (const float*)d_in[3];
    const float* out_w = (const float*)d_in[4];
    const float* out_b = (const float*)d_in[5];
    float* outp = (float*)d_out;

    gemm_qkv   <<<dim3(QKVN/128, MTOK/128), 256>>>(x, qkv_w, qkv_b);
    rope_kernel<<<(2*NB*SEQ*NHEAD*64)/256, 256>>>();
    gemm_scores<<<dim3(SEQ/128, SEQ/128, NBH), 256>>>(amask);
    softmax_rows<<<NBH*SEQ, 256>>>();
    gemm_pv    <<<dim3(SEQ/128, NBH), 256>>>();
    gemm_out   <<<dim3(HID/128, MTOK/128), 256>>>(out_w, out_b, outp);
}

// round 11
// speedup vs baseline: 1.9552x; 1.9534x over previous
#include <cuda_runtime.h>
#include <cuda_bf16.h>
#include <stdint.h>
#include <math.h>

#define NB    2
#define SEQ   2048
#define HID   2048
#define NHEAD 16
#define HD    128
#define NBH   (NB*NHEAD)     // 32
#define MTOK  (NB*SEQ)       // 4096
#define QKVN  (3*HID)        // 6144
#define NEG_BIG (-1e30f)
#define SM_SCALE 0.08838834764831845f

typedef __nv_bfloat16 bf16;

// ---------------- static device scratch ----------------
static __device__ float g_qkv   [(size_t)MTOK * QKVN];
static __device__ float g_scores[(size_t)NBH * SEQ * SEQ];
static __device__ bf16 g_xhi [(size_t)MTOK*HID],  g_xlo [(size_t)MTOK*HID];
static __device__ bf16 g_whi [(size_t)QKVN*HID],  g_wlo [(size_t)QKVN*HID];
static __device__ bf16 g_owhi[(size_t)HID*HID],   g_owlo[(size_t)HID*HID];
static __device__ bf16 g_qhi [(size_t)NBH*SEQ*HD], g_qlo [(size_t)NBH*SEQ*HD];
static __device__ bf16 g_khi [(size_t)NBH*SEQ*HD], g_klo [(size_t)NBH*SEQ*HD];
static __device__ bf16 g_vthi[(size_t)NBH*HD*SEQ], g_vtlo[(size_t)NBH*HD*SEQ];
static __device__ bf16 g_phi [(size_t)NBH*SEQ*SEQ], g_plo [(size_t)NBH*SEQ*SEQ];
static __device__ bf16 g_ahi [(size_t)MTOK*HID],  g_alo [(size_t)MTOK*HID];

// ---------------- helpers ----------------
__device__ __forceinline__ uint32_t s2u(const void* p) {
    uint32_t a;
    asm("{ .reg .u64 t; cvta.to.shared.u64 t, %1; cvt.u32.u64 %0, t; }" : "=r"(a) : "l"(p));
    return a;
}
__device__ __forceinline__ void cpa16(uint32_t sa, const void* g) {
    asm volatile("cp.async.cg.shared.global [%0], [%1], 16;" :: "r"(sa), "l"(g));
}
__device__ __forceinline__ void cpa_commit_wait() {
    asm volatile("cp.async.commit_group;" ::: "memory");
    asm volatile("cp.async.wait_group 0;" ::: "memory");
}
__device__ __forceinline__ uint32_t lds32(uint32_t a) {
    uint32_t v;
    asm volatile("ld.shared.b32 %0, [%1];" : "=r"(v) : "r"(a));
    return v;
}
__device__ __forceinline__ void hmma(float (&d)[4], const uint32_t (&a)[4], const uint32_t (&b)[2]) {
    asm volatile("mma.sync.aligned.m16n8k16.row.col.f32.bf16.bf16.f32 "
        "{%0,%1,%2,%3}, {%4,%5,%6,%7}, {%8,%9}, {%0,%1,%2,%3};"
        : "+f"(d[0]), "+f"(d[1]), "+f"(d[2]), "+f"(d[3])
        : "r"(a[0]), "r"(a[1]), "r"(a[2]), "r"(a[3]), "r"(b[0]), "r"(b[1]));
}
__device__ __forceinline__ void split2(float2 v, uint32_t& hi, uint32_t& lo) {
    __nv_bfloat162 h = __float22bfloat162_rn(v);
    float2 hf = __bfloat1622float2(h);
    __nv_bfloat162 l = __float22bfloat162_rn(make_float2(v.x - hf.x, v.y - hf.y));
    hi = *reinterpret_cast<uint32_t*>(&h);
    lo = *reinterpret_cast<uint32_t*>(&l);
}

// SMEM tiles: 128 rows x 64 bf16, padded stride 72 bf16 = 144 B
#define LDSB 144u
#define TILE_B (128u*LDSB)        // 18432
#define OFF_AHI 0u
#define OFF_ALO TILE_B
#define OFF_BHI (2u*TILE_B)
#define OFF_BLO (3u*TILE_B)
#define DYN_SMEM (4*18432)        // 73728

// Fill one 128x64-bf16 tile via cp.async (256 threads, 4x16B each)
__device__ __forceinline__ void fillt(uint32_t sbase, const bf16* __restrict__ src,
                                      size_t ld, int k0) {
    const int t = threadIdx.x;
    const int r = t >> 1, seg = t & 1;
    const char* g = (const char*)(src + (size_t)r * ld + (size_t)k0 + seg * 32);
    const uint32_t d0 = sbase + (uint32_t)r * LDSB + (uint32_t)seg * 64u;
    #pragma unroll
    for (int gi = 0; gi < 4; gi++)
        cpa16(d0 + gi * 16u, g + gi * 16);
}

// Warp-fragment mainloop: acc += (Ahi+Alo) @ (Bhi+Blo)^T  (drop lo*lo)
// CTA tile 128x128, 8 warps each 64x32 (4x4 m16n8 tiles), K-chunk 64.
__device__ void run_mma(uint32_t sm0,
        const bf16* __restrict__ Ahi, const bf16* __restrict__ Alo, size_t lda,
        const bf16* __restrict__ Bhi, const bf16* __restrict__ Blo, size_t ldb,
        int nc, float (&acc)[4][4][4])
{
    const int lane = threadIdx.x & 31, warp = threadIdx.x >> 5;
    const int wr = warp >> 2, wc = warp & 3;
    const int g = lane >> 2, i2 = (lane & 3) * 2;

    for (int c = 0; c < nc; c++) {
        const int k0 = c * 64;
        fillt(sm0 + OFF_AHI, Ahi, lda, k0);
        fillt(sm0 + OFF_ALO, Alo, lda, k0);
        fillt(sm0 + OFF_BHI, Bhi, ldb, k0);
        fillt(sm0 + OFF_BLO, Blo, ldb, k0);
        cpa_commit_wait();
        __syncthreads();

        #pragma unroll
        for (int ks = 0; ks < 4; ks++) {
            const uint32_t ca = (uint32_t)((ks * 16 + i2) * 2);
            uint32_t ahi[4][4], alo[4][4];
            #pragma unroll
            for (int mt = 0; mt < 4; mt++) {
                uint32_t r0 = (uint32_t)(wr * 64 + mt * 16 + g);
                uint32_t ad = sm0 + OFF_AHI + r0 * LDSB + ca;
                ahi[mt][0] = lds32(ad);
                ahi[mt][1] = lds32(ad + 8u * LDSB);
                ahi[mt][2] = lds32(ad + 16u);
                ahi[mt][3] = lds32(ad + 8u * LDSB + 16u);
                uint32_t al = ad + (OFF_ALO - OFF_AHI);
                alo[mt][0] = lds32(al);
                alo[mt][1] = lds32(al + 8u * LDSB);
                alo[mt][2] = lds32(al + 16u);
                alo[mt][3] = lds32(al + 8u * LDSB + 16u);
            }
            #pragma unroll
            for (int nt = 0; nt < 4; nt++) {
                uint32_t rn = (uint32_t)(wc * 32 + nt * 8 + g);
                uint32_t bd = sm0 + OFF_BHI + rn * LDSB + ca;
                uint32_t bhi[2] = { lds32(bd), lds32(bd + 16u) };
                uint32_t bl0 = bd + (OFF_BLO - OFF_BHI);
                uint32_t blo[2] = { lds32(bl0), lds32(bl0 + 16u) };
                #pragma unroll
                for (int mt = 0; mt < 4; mt++) {
                    hmma(acc[mt][nt], ahi[mt], bhi);
                    hmma(acc[mt][nt], alo[mt], bhi);
                    hmma(acc[mt][nt], ahi[mt], blo);
                }
            }
        }
        __syncthreads();
    }
}

// ---------------- conversion kernels ----------------
__device__ __forceinline__ void conv_body(const float4* __restrict__ in,
                                          bf16* hi, bf16* lo, int n4) {
    int i = blockIdx.x * blockDim.x + threadIdx.x;
    if (i >= n4) return;
    float4 v = in[i];
    uint32_t h0, l0, h1, l1;
    split2(make_float2(v.x, v.y), h0, l0);
    split2(make_float2(v.z, v.w), h1, l1);
    *(uint2*)(hi + (size_t)i * 4) = make_uint2(h0, h1);
    *(uint2*)(lo + (size_t)i * 4) = make_uint2(l0, l1);
}
__global__ __launch_bounds__(256) void conv_x (const float* in) { conv_body((const float4*)in, g_xhi,  g_xlo,  MTOK*HID/4); }
__global__ __launch_bounds__(256) void conv_w (const float* in) { conv_body((const float4*)in, g_whi,  g_wlo,  QKVN*HID/4); }
__global__ __launch_bounds__(256) void conv_ow(const float* in) { conv_body((const float4*)in, g_owhi, g_owlo, HID*HID/4); }

// ---------------- GEMM 1: QKV projection ----------------
__global__ __launch_bounds__(256, 2)
void gemm_qkv_tc(const float* __restrict__ bias)
{
    extern __shared__ uint8_t dsm[];
    uint32_t sm0 = s2u(dsm);
    const int bm = blockIdx.y * 128, bn = blockIdx.x * 128;
    float acc[4][4][4] = {};
    run_mma(sm0, g_xhi + (size_t)bm * HID, g_xlo + (size_t)bm * HID, HID,
                 g_whi + (size_t)bn * HID, g_wlo + (size_t)bn * HID, HID, HID/64, acc);
    const int lane = threadIdx.x & 31, warp = threadIdx.x >> 5;
    const int wr = warp >> 2, wc = warp & 3;
    const int g = lane >> 2, i2 = (lane & 3) * 2;
    #pragma unroll
    for (int mt = 0; mt < 4; mt++)
    #pragma unroll
    for (int nt = 0; nt < 4; nt++) {
        int r0 = bm + wr*64 + mt*16 + g;
        int cc = bn + wc*32 + nt*8 + i2;
        float2 v0 = make_float2(acc[mt][nt][0] + bias[cc], acc[mt][nt][1] + bias[cc+1]);
        float2 v1 = make_float2(acc[mt][nt][2] + bias[cc], acc[mt][nt][3] + bias[cc+1]);
        *(float2*)(g_qkv + (size_t)r0 * QKVN + cc)       = v0;
        *(float2*)(g_qkv + (size_t)(r0+8) * QKVN + cc)   = v1;
    }
}

// ---------------- RoPE + q/k split ----------------
__global__ __launch_bounds__(256)
void rope_conv()
{
    int idx = blockIdx.x * 256 + threadIdx.x;
    const int i = idx & 63;  idx >>= 6;
    const int h = idx & 15;  idx >>= 4;
    const int s = idx & (SEQ - 1); idx >>= 11;
    const int b = idx & 1;
    const int which = idx >> 1;                 // 0=q, 1=k
    const size_t base = (size_t)(b * SEQ + s) * QKVN + which * HID + h * HD;
    // Reference: emb[d] = pos * f_{d mod 64}  (freqs concatenated twice!)
    const int j0 = (2*i)     & 63;              // <-- the & 63 that R8 dropped
    const int j1 = (2*i + 1) & 63;
    const float C = 0.20762050593045013f;       // log2(10000)/64
    float f0 = exp2f(-(float)j0 * C);
    float f1 = exp2f(-(float)j1 * C);
    float c0, s0, c1, s1;
    sincosf((float)s * f0, &s0, &c0);
    sincosf((float)s * f1, &s1, &c1);
    float x0 = g_qkv[base + 2*i];
    float x1 = g_qkv[base + 2*i + 1];
    float y0 = x0 * c0 - x1 * s0;
    float y1 = x1 * c1 + x0 * s1;
    const int z = b * NHEAD + h;
    const size_t o = ((size_t)z * SEQ + s) * HD + 2*i;
    uint32_t hh, ll;
    split2(make_float2(y0, y1), hh, ll);
    if (which == 0) { *(uint32_t*)(g_qhi + o) = hh; *(uint32_t*)(g_qlo + o) = ll; }
    else            { *(uint32_t*)(g_khi + o) = hh; *(uint32_t*)(g_klo + o) = ll; }
}

// ---------------- V transpose + split: [s,d] -> [d,s] ----------------
__global__ __launch_bounds__(256)
void vtrans()
{
    __shared__ float t[32][33];
    const int z = blockIdx.z, b = z >> 4, h = z & 15;
    const int s0 = blockIdx.x * 32, d0 = blockIdx.y * 32;
    const int tx = threadIdx.x & 31, ty = threadIdx.x >> 5;   // 32x8
    #pragma unroll
    for (int j = 0; j < 4; j++) {
        int s = s0 + ty + j * 8;
        t[ty + j*8][tx] = g_qkv[(size_t)(b * SEQ + s) * QKVN + 2*HID + h * HD + d0 + tx];
    }
    __syncthreads();
    #pragma unroll
    for (int j = 0; j < 4; j++) {
        int d = d0 + ty + j * 8;
        float val = t[tx][ty + j*8];
        bf16 hb = __float2bfloat16(val);
        size_t o = ((size_t)z * HD + d) * SEQ + s0 + tx;
        g_vthi[o] = hb;
        g_vtlo[o] = __float2bfloat16(val - __bfloat162float(hb));
    }
}

// ---------------- GEMM 2: scores (lower-tri tiles only) ----------------
__global__ __launch_bounds__(256, 2)
void gemm_scores_tc(const int* __restrict__ amask)
{
    if (blockIdx.x > blockIdx.y) return;
    extern __shared__ uint8_t dsm[];
    uint32_t sm0 = s2u(dsm);
    const int z = blockIdx.z, b = z >> 4;
    const int bm = blockIdx.y * 128, bn = blockIdx.x * 128;
    float acc[4][4][4] = {};
    run_mma(sm0, g_qhi + ((size_t)z * SEQ + bm) * HD, g_qlo + ((size_t)z * SEQ + bm) * HD, HD,
                 g_khi + ((size_t)z * SEQ + bn) * HD, g_klo + ((size_t)z * SEQ + bn) * HD, HD, 2, acc);
    const int lane = threadIdx.x & 31, warp = threadIdx.x >> 5;
    const int wr = warp >> 2, wc = warp & 3;
    const int g = lane >> 2, i2 = (lane & 3) * 2;
    const int* am = amask + b * SEQ;
    #pragma unroll
    for (int mt = 0; mt < 4; mt++)
    #pragma unroll
    for (int nt = 0; nt < 4; nt++) {
        int r0 = bm + wr*64 + mt*16 + g;
        int cc = bn + wc*32 + nt*8 + i2;
        float m0 = (am[cc]   != 0) ? 1.f : 0.f;
        float m1 = (am[cc+1] != 0) ? 1.f : 0.f;
        #pragma unroll
        for (int half = 0; half < 2; half++) {
            int r = r0 + half * 8;
            float v0 = acc[mt][nt][half*2+0] * SM_SCALE;
            float v1 = acc[mt][nt][half*2+1] * SM_SCALE;
            if (cc   > r || m0 == 0.f) v0 = NEG_BIG;
            if (cc+1 > r || m1 == 0.f) v1 = NEG_BIG;
            *(float2*)(g_scores + ((size_t)z * SEQ + r) * SEQ + cc) = make_float2(v0, v1);
        }
    }
}

// ---------------- softmax over causal prefix + P split ----------------
__global__ __launch_bounds__(256)
void softmax_pconv()
{
    const int bi = blockIdx.x;
    const int r = bi & (SEQ - 1);
    const int z = bi >> 11;
    const int ncols = ((r >> 7) + 1) << 7;       // causal bound, tile-rounded
    const size_t rowbase = ((size_t)z * SEQ + r) * SEQ;
    const float* p = g_scores + rowbase;
    const int tid = threadIdx.x;
    __shared__ float red[256];

    const bool act = tid * 8 < ncols;
    float v[8];
    float mx = NEG_BIG;
    if (act) {
        float4 u0 = *(const float4*)(p + tid*8);
        float4 u1 = *(const float4*)(p + tid*8 + 4);
        v[0]=u0.x; v[1]=u0.y; v[2]=u0.z; v[3]=u0.w;
        v[4]=u1.x; v[5]=u1.y; v[6]=u1.z; v[7]=u1.w;
        #pragma unroll
        for (int i = 0; i < 8; i++) mx = fmaxf(mx, v[i]);
    }
    red[tid] = mx; __syncthreads();
    for (int off = 128; off > 0; off >>= 1) {
        if (tid < off) red[tid] = fmaxf(red[tid], red[tid + off]);
        __syncthreads();
    }
    mx = red[0]; __syncthreads();

    float sum = 0.f;
    if (act) {
        #pragma unroll
        for (int i = 0; i < 8; i++) { v[i] = expf(v[i] - mx); sum += v[i]; }
    }
    red[tid] = sum; __syncthreads();
    for (int off = 128; off > 0; off >>= 1) {
        if (tid < off) red[tid] += red[tid + off];
        __syncthreads();
    }
    float inv = 1.0f / red[0];

    if (act) {
        bf16* ph = g_phi + rowbase + tid*8;
        bf16* pl = g_plo + rowbase + tid*8;
        #pragma unroll
        for (int i = 0; i < 8; i += 2) {
            uint32_t hh, ll;
            split2(make_float2(v[i]*inv, v[i+1]*inv), hh, ll);
            *(uint32_t*)(ph + i) = hh;
            *(uint32_t*)(pl + i) = ll;
        }
    }
}

// ---------------- GEMM 3: attn = P @ V  (B = V^T, K over seq) ----------------
__global__ __launch_bounds__(256, 2)
void gemm_pv_tc()
{
    extern __shared__ uint8_t dsm[];
    uint32_t sm0 = s2u(dsm);
    const int z = blockIdx.y, b = z >> 4, h = z & 15;
    const int bm = blockIdx.x * 128;
    const int nc = (bm + 128) / 64;              // causal truncation
    float acc[4][4][4] = {};
    run_mma(sm0, g_phi + ((size_t)z * SEQ + bm) * SEQ, g_plo + ((size_t)z * SEQ + bm) * SEQ, SEQ,
                 g_vthi + (size_t)z * HD * SEQ,        g_vtlo + (size_t)z * HD * SEQ,        SEQ, nc, acc);
    const int lane = threadIdx.x & 31, warp = threadIdx.x >> 5;
    const int wr = warp >> 2, wc = warp & 3;
    const int g = lane >> 2, i2 = (lane & 3) * 2;
    #pragma unroll
    for (int mt = 0; mt < 4; mt++)
    #pragma unroll
    for (int nt = 0; nt < 4; nt++) {
        int r0 = bm + wr*64 + mt*16 + g;
        int cc = wc*32 + nt*8 + i2;
        #pragma unroll
        for (int half = 0; half < 2; half++) {
            int r = r0 + half * 8;
            size_t o = (size_t)(b * SEQ + r) * HID + h * HD + cc;
            uint32_t hh, ll;
            split2(make_float2(acc[mt][nt][half*2+0], acc[mt][nt][half*2+1]), hh, ll);
            *(uint32_t*)(g_ahi + o) = hh;
            *(uint32_t*)(g_alo + o) = ll;
        }
    }
}

// ---------------- GEMM 4: out = attn @ out_w^T + out_b ----------------
__global__ __launch_bounds__(256, 2)
void gemm_out_tc(const float* __restrict__ bias, float* __restrict__ outp)
{
    extern __shared__ uint8_t dsm[];
    uint32_t sm0 = s2u(dsm);
    const int bm = blockIdx.y * 128, bn = blockIdx.x * 128;
    float acc[4][4][4] = {};
    run_mma(sm0, g_ahi + (size_t)bm * HID, g_alo + (size_t)bm * HID, HID,
                 g_owhi + (size_t)bn * HID, g_owlo + (size_t)bn * HID, HID, HID/64, acc);
    const int lane = threadIdx.x & 31, warp = threadIdx.x >> 5;
    const int wr = warp >> 2, wc = warp & 3;
    const int g = lane >> 2, i2 = (lane & 3) * 2;
    #pragma unroll
    for (int mt = 0; mt < 4; mt++)
    #pragma unroll
    for (int nt = 0; nt < 4; nt++) {
        int r0 = bm + wr*64 + mt*16 + g;
        int cc = bn + wc*32 + nt*8 + i2;
        float2 v0 = make_float2(acc[mt][nt][0] + bias[cc], acc[mt][nt][1] + bias[cc+1]);
        float2 v1 = make_float2(acc[mt][nt][2] + bias[cc], acc[mt][nt][3] + bias[cc+1]);
        *(float2*)(outp + (size_t)r0 * HID + cc)     = v0;
        *(float2*)(outp + (size_t)(r0+8) * HID + cc) = v1;
    }
}

// ---------------------------------------------------------------------------
extern "C" void kernel_launch(void* const* d_in, const int* in_sizes, int n_in,
                              void* d_out, int out_size)
{
    (void)in_sizes; (void)n_in; (void)out_size;
    const int*   amask = (const int*)  d_in[1];
    const float* qkv_b = (const float*)d_in[3];
    const float* out_b = (const float*)d_in[5];
    float* outp = (float*)d_out;

    cudaFuncSetAttribute(gemm_qkv_tc,    cudaFuncAttributeMaxDynamicSharedMemorySize, DYN_SMEM);
    cudaFuncSetAttribute(gemm_scores_tc, cudaFuncAttributeMaxDynamicSharedMemorySize, DYN_SMEM);
    cudaFuncSetAttribute(gemm_pv_tc,     cudaFuncAttributeMaxDynamicSharedMemorySize, DYN_SMEM);
    cudaFuncSetAttribute(gemm_out_tc,    cudaFuncAttributeMaxDynamicSharedMemorySize, DYN_SMEM);

    conv_x <<<MTOK*HID/4/256, 256>>>((const float*)d_in[0]);
    conv_w <<<QKVN*HID/4/256, 256>>>((const float*)d_in[2]);
    conv_ow<<<HID*HID/4/256, 256>>>((const float*)d_in[4]);
    gemm_qkv_tc   <<<dim3(QKVN/128, MTOK/128), 256, DYN_SMEM>>>(qkv_b);
    rope_conv     <<<(2*NB*SEQ*NHEAD*64)/256, 256>>>();
    vtrans        <<<dim3(SEQ/32, HD/32, NBH), 256>>>();
    gemm_scores_tc<<<dim3(SEQ/128, SEQ/128, NBH), 256, DYN_SMEM>>>(amask);
    softmax_pconv <<<NBH*SEQ, 256>>>();
    gemm_pv_tc    <<<dim3(SEQ/128, NBH), 256, DYN_SMEM>>>();
    gemm_out_tc   <<<dim3(HID/128, MTOK/128), 256, DYN_SMEM>>>(out_b, outp);
}

// round 12
// speedup vs baseline: 2.2299x; 1.1405x over previous
#include <cuda_runtime.h>
#include <cuda_bf16.h>
#include <stdint.h>
#include <math.h>

#define NB    2
#define SEQ   2048
#define HID   2048
#define NHEAD 16
#define HD    128
#define NBH   (NB*NHEAD)     // 32
#define MTOK  (NB*SEQ)       // 4096
#define QKVN  (3*HID)        // 6144
#define NEG_BIG (-1e30f)
#define SM_SCALE 0.08838834764831845f

typedef __nv_bfloat16 bf16;

// ---------------- static device scratch ----------------
static __device__ float g_qkv   [(size_t)MTOK * QKVN];
static __device__ float g_scores[(size_t)NBH * SEQ * SEQ];
static __device__ bf16 g_xhi [(size_t)MTOK*HID],  g_xlo [(size_t)MTOK*HID];
static __device__ bf16 g_whi [(size_t)QKVN*HID],  g_wlo [(size_t)QKVN*HID];
static __device__ bf16 g_owhi[(size_t)HID*HID],   g_owlo[(size_t)HID*HID];
static __device__ bf16 g_qhi [(size_t)NBH*SEQ*HD], g_qlo [(size_t)NBH*SEQ*HD];
static __device__ bf16 g_khi [(size_t)NBH*SEQ*HD], g_klo [(size_t)NBH*SEQ*HD];
static __device__ bf16 g_vthi[(size_t)NBH*HD*SEQ], g_vtlo[(size_t)NBH*HD*SEQ];
static __device__ bf16 g_phi [(size_t)NBH*SEQ*SEQ], g_plo [(size_t)NBH*SEQ*SEQ];
static __device__ bf16 g_ahi [(size_t)MTOK*HID],  g_alo [(size_t)MTOK*HID];

// ---------------- helpers ----------------
__device__ __forceinline__ uint32_t s2u(const void* p) {
    uint32_t a;
    asm("{ .reg .u64 t; cvta.to.shared.u64 t, %1; cvt.u32.u64 %0, t; }" : "=r"(a) : "l"(p));
    return a;
}
__device__ __forceinline__ void cpa16(uint32_t sa, const void* g) {
    asm volatile("cp.async.cg.shared.global [%0], [%1], 16;" :: "r"(sa), "l"(g));
}
__device__ __forceinline__ void ldmx4(uint32_t (&r)[4], uint32_t a) {
    asm volatile("ldmatrix.sync.aligned.m8n8.x4.shared.b16 {%0,%1,%2,%3}, [%4];"
        : "=r"(r[0]), "=r"(r[1]), "=r"(r[2]), "=r"(r[3]) : "r"(a));
}
__device__ __forceinline__ void hmma(float (&d)[4], const uint32_t (&a)[4],
                                     uint32_t b0, uint32_t b1) {
    asm volatile("mma.sync.aligned.m16n8k16.row.col.f32.bf16.bf16.f32 "
        "{%0,%1,%2,%3}, {%4,%5,%6,%7}, {%8,%9}, {%0,%1,%2,%3};"
        : "+f"(d[0]), "+f"(d[1]), "+f"(d[2]), "+f"(d[3])
        : "r"(a[0]), "r"(a[1]), "r"(a[2]), "r"(a[3]), "r"(b0), "r"(b1));
}
__device__ __forceinline__ void split2(float2 v, uint32_t& hi, uint32_t& lo) {
    __nv_bfloat162 h = __float22bfloat162_rn(v);
    float2 hf = __bfloat1622float2(h);
    __nv_bfloat162 l = __float22bfloat162_rn(make_float2(v.x - hf.x, v.y - hf.y));
    hi = *reinterpret_cast<uint32_t*>(&h);
    lo = *reinterpret_cast<uint32_t*>(&l);
}

// SMEM: 2 stages, each 4 tiles of 128x32 bf16, row stride 80B (64B data + 16B pad)
#define LDSB32  80u
#define TILE32  (128u*LDSB32)     // 10240
#define OFF_AHI 0u
#define OFF_ALO TILE32
#define OFF_BHI (2u*TILE32)
#define OFF_BLO (3u*TILE32)
#define STAGE_B (4u*TILE32)       // 40960
#define DYN_SMEM (2*40960)        // 81920 -> 2 CTAs/SM

// Fill one 128x32-bf16 tile (2 cp.async of 16B per thread)
__device__ __forceinline__ void fillt32(uint32_t sbase, const bf16* __restrict__ src,
                                        size_t ld, int k0) {
    const int t = threadIdx.x;
    const int r = t >> 1, seg = t & 1;
    const char* g = (const char*)(src + (size_t)r * ld + (size_t)k0 + seg * 16);
    const uint32_t d = sbase + (uint32_t)r * LDSB32 + (uint32_t)seg * 32u;
    cpa16(d, g);
    cpa16(d + 16u, g + 16);
}

__device__ __forceinline__ void fill_stage(uint32_t sb,
        const bf16* Ahi, const bf16* Alo, size_t lda,
        const bf16* Bhi, const bf16* Blo, size_t ldb, int k0) {
    fillt32(sb + OFF_AHI, Ahi, lda, k0);
    fillt32(sb + OFF_ALO, Alo, lda, k0);
    fillt32(sb + OFF_BHI, Bhi, ldb, k0);
    fillt32(sb + OFF_BLO, Blo, ldb, k0);
    asm volatile("cp.async.commit_group;" ::: "memory");
}

// Double-buffered warp-fragment mainloop, ldmatrix loads.
// acc += (Ahi+Alo) @ (Bhi+Blo)^T  (drop lo*lo). CTA 128x128, 8 warps 64x32 each.
__device__ void run_mma(uint32_t sm0,
        const bf16* __restrict__ Ahi, const bf16* __restrict__ Alo, size_t lda,
        const bf16* __restrict__ Bhi, const bf16* __restrict__ Blo, size_t ldb,
        int nc, float (&acc)[4][4][4])
{
    const int lane = threadIdx.x & 31, warp = threadIdx.x >> 5;
    const int wr = warp >> 2, wc = warp & 3;
    const int g8 = lane & 7, sel = lane >> 3;

    // A ldmatrix lane address components (within stage, tile-relative):
    //   matrices: m0=(rows 0-7,k0-7), m1=(rows 8-15,k0-7), m2=(rows 0-7,k8-15), m3=(rows 8-15,k8-15)
    const uint32_t a_row = (uint32_t)(wr * 64 + (sel & 1) * 8 + g8);
    const uint32_t a_col = (uint32_t)((sel >> 1) * 16);
    // B: m0=(n 0-7,k0-7), m1=(n 0-7,k8-15), m2=(n 8-15,k0-7), m3=(n 8-15,k8-15)
    const uint32_t b_row = (uint32_t)(wc * 32 + (sel >> 1) * 8 + g8);
    const uint32_t b_col = (uint32_t)((sel & 1) * 16);

    fill_stage(sm0, Ahi, Alo, lda, Bhi, Blo, ldb, 0);

    for (int c = 0; c < nc; c++) {
        const uint32_t sb = sm0 + (uint32_t)(c & 1) * STAGE_B;
        if (c + 1 < nc) {
            fill_stage(sm0 + (uint32_t)((c + 1) & 1) * STAGE_B,
                       Ahi, Alo, lda, Bhi, Blo, ldb, (c + 1) * 32);
            asm volatile("cp.async.wait_group 1;" ::: "memory");
        } else {
            asm volatile("cp.async.wait_group 0;" ::: "memory");
        }
        __syncthreads();

        #pragma unroll
        for (int ks = 0; ks < 2; ks++) {
            const uint32_t kb = (uint32_t)(ks * 32);
            uint32_t ahi[4][4], alo[4][4];
            #pragma unroll
            for (int mt = 0; mt < 4; mt++) {
                uint32_t ad = sb + (a_row + mt * 16) * LDSB32 + a_col + kb;
                ldmx4(ahi[mt], ad + OFF_AHI);
                ldmx4(alo[mt], ad + OFF_ALO);
            }
            #pragma unroll
            for (int ntp = 0; ntp < 2; ntp++) {
                uint32_t bd = sb + (b_row + ntp * 16) * LDSB32 + b_col + kb;
                uint32_t bhi[4], blo[4];
                ldmx4(bhi, bd + OFF_BHI);
                ldmx4(blo, bd + OFF_BLO);
                #pragma unroll
                for (int mt = 0; mt < 4; mt++) {
                    hmma(acc[mt][2*ntp],   ahi[mt], bhi[0], bhi[1]);
                    hmma(acc[mt][2*ntp],   alo[mt], bhi[0], bhi[1]);
                    hmma(acc[mt][2*ntp],   ahi[mt], blo[0], blo[1]);
                    hmma(acc[mt][2*ntp+1], ahi[mt], bhi[2], bhi[3]);
                    hmma(acc[mt][2*ntp+1], alo[mt], bhi[2], bhi[3]);
                    hmma(acc[mt][2*ntp+1], ahi[mt], blo[2], blo[3]);
                }
            }
        }
        __syncthreads();
    }
}

// ---------------- conversion kernels ----------------
__device__ __forceinline__ void conv_body(const float4* __restrict__ in,
                                          bf16* hi, bf16* lo, int n4) {
    int i = blockIdx.x * blockDim.x + threadIdx.x;
    if (i >= n4) return;
    float4 v = in[i];
    uint32_t h0, l0, h1, l1;
    split2(make_float2(v.x, v.y), h0, l0);
    split2(make_float2(v.z, v.w), h1, l1);
    *(uint2*)(hi + (size_t)i * 4) = make_uint2(h0, h1);
    *(uint2*)(lo + (size_t)i * 4) = make_uint2(l0, l1);
}
__global__ __launch_bounds__(256) void conv_x (const float* in) { conv_body((const float4*)in, g_xhi,  g_xlo,  MTOK*HID/4); }
__global__ __launch_bounds__(256) void conv_w (const float* in) { conv_body((const float4*)in, g_whi,  g_wlo,  QKVN*HID/4); }
__global__ __launch_bounds__(256) void conv_ow(const float* in) { conv_body((const float4*)in, g_owhi, g_owlo, HID*HID/4); }

// ---------------- GEMM 1: QKV projection ----------------
__global__ __launch_bounds__(256, 2)
void gemm_qkv_tc(const float* __restrict__ bias)
{
    extern __shared__ uint8_t dsm[];
    uint32_t sm0 = s2u(dsm);
    const int bm = blockIdx.y * 128, bn = blockIdx.x * 128;
    float acc[4][4][4] = {};
    run_mma(sm0, g_xhi + (size_t)bm * HID, g_xlo + (size_t)bm * HID, HID,
                 g_whi + (size_t)bn * HID, g_wlo + (size_t)bn * HID, HID, HID/32, acc);
    const int lane = threadIdx.x & 31, warp = threadIdx.x >> 5;
    const int wr = warp >> 2, wc = warp & 3;
    const int g = lane >> 2, i2 = (lane & 3) * 2;
    #pragma unroll
    for (int mt = 0; mt < 4; mt++)
    #pragma unroll
    for (int nt = 0; nt < 4; nt++) {
        int r0 = bm + wr*64 + mt*16 + g;
        int cc = bn + wc*32 + nt*8 + i2;
        float2 v0 = make_float2(acc[mt][nt][0] + bias[cc], acc[mt][nt][1] + bias[cc+1]);
        float2 v1 = make_float2(acc[mt][nt][2] + bias[cc], acc[mt][nt][3] + bias[cc+1]);
        *(float2*)(g_qkv + (size_t)r0 * QKVN + cc)       = v0;
        *(float2*)(g_qkv + (size_t)(r0+8) * QKVN + cc)   = v1;
    }
}

// ---------------- RoPE + q/k split ----------------
__global__ __launch_bounds__(256)
void rope_conv()
{
    int idx = blockIdx.x * 256 + threadIdx.x;
    const int i = idx & 63;  idx >>= 6;
    const int h = idx & 15;  idx >>= 4;
    const int s = idx & (SEQ - 1); idx >>= 11;
    const int b = idx & 1;
    const int which = idx >> 1;                 // 0=q, 1=k
    const size_t base = (size_t)(b * SEQ + s) * QKVN + which * HID + h * HD;
    // Reference: emb[d] = pos * f_{d mod 64}  (freqs concatenated twice)
    const int j0 = (2*i)     & 63;
    const int j1 = (2*i + 1) & 63;
    const float C = 0.20762050593045013f;       // log2(10000)/64
    float f0 = exp2f(-(float)j0 * C);
    float f1 = exp2f(-(float)j1 * C);
    float c0, s0, c1, s1;
    sincosf((float)s * f0, &s0, &c0);
    sincosf((float)s * f1, &s1, &c1);
    float x0 = g_qkv[base + 2*i];
    float x1 = g_qkv[base + 2*i + 1];
    float y0 = x0 * c0 - x1 * s0;
    float y1 = x1 * c1 + x0 * s1;
    const int z = b * NHEAD + h;
    const size_t o = ((size_t)z * SEQ + s) * HD + 2*i;
    uint32_t hh, ll;
    split2(make_float2(y0, y1), hh, ll);
    if (which == 0) { *(uint32_t*)(g_qhi + o) = hh; *(uint32_t*)(g_qlo + o) = ll; }
    else            { *(uint32_t*)(g_khi + o) = hh; *(uint32_t*)(g_klo + o) = ll; }
}

// ---------------- V transpose + split: [s,d] -> [d,s] ----------------
__global__ __launch_bounds__(256)
void vtrans()
{
    __shared__ float t[32][33];
    const int z = blockIdx.z, b = z >> 4, h = z & 15;
    const int s0 = blockIdx.x * 32, d0 = blockIdx.y * 32;
    const int tx = threadIdx.x & 31, ty = threadIdx.x >> 5;   // 32x8
    #pragma unroll
    for (int j = 0; j < 4; j++) {
        int s = s0 + ty + j * 8;
        t[ty + j*8][tx] = g_qkv[(size_t)(b * SEQ + s) * QKVN + 2*HID + h * HD + d0 + tx];
    }
    __syncthreads();
    #pragma unroll
    for (int j = 0; j < 4; j++) {
        int d = d0 + ty + j * 8;
        float val = t[tx][ty + j*8];
        bf16 hb = __float2bfloat16(val);
        size_t o = ((size_t)z * HD + d) * SEQ + s0 + tx;
        g_vthi[o] = hb;
        g_vtlo[o] = __float2bfloat16(val - __bfloat162float(hb));
    }
}

// ---------------- GEMM 2: scores (lower-tri tiles only) ----------------
__global__ __launch_bounds__(256, 2)
void gemm_scores_tc(const int* __restrict__ amask)
{
    if (blockIdx.x > blockIdx.y) return;
    extern __shared__ uint8_t dsm[];
    uint32_t sm0 = s2u(dsm);
    const int z = blockIdx.z, b = z >> 4;
    const int bm = blockIdx.y * 128, bn = blockIdx.x * 128;
    float acc[4][4][4] = {};
    run_mma(sm0, g_qhi + ((size_t)z * SEQ + bm) * HD, g_qlo + ((size_t)z * SEQ + bm) * HD, HD,
                 g_khi + ((size_t)z * SEQ + bn) * HD, g_klo + ((size_t)z * SEQ + bn) * HD, HD, HD/32, acc);
    const int lane = threadIdx.x & 31, warp = threadIdx.x >> 5;
    const int wr = warp >> 2, wc = warp & 3;
    const int g = lane >> 2, i2 = (lane & 3) * 2;
    const int* am = amask + b * SEQ;
    #pragma unroll
    for (int mt = 0; mt < 4; mt++)
    #pragma unroll
    for (int nt = 0; nt < 4; nt++) {
        int r0 = bm + wr*64 + mt*16 + g;
        int cc = bn + wc*32 + nt*8 + i2;
        float m0 = (am[cc]   != 0) ? 1.f : 0.f;
        float m1 = (am[cc+1] != 0) ? 1.f : 0.f;
        #pragma unroll
        for (int half = 0; half < 2; half++) {
            int r = r0 + half * 8;
            float v0 = acc[mt][nt][half*2+0] * SM_SCALE;
            float v1 = acc[mt][nt][half*2+1] * SM_SCALE;
            if (cc   > r || m0 == 0.f) v0 = NEG_BIG;
            if (cc+1 > r || m1 == 0.f) v1 = NEG_BIG;
            *(float2*)(g_scores + ((size_t)z * SEQ + r) * SEQ + cc) = make_float2(v0, v1);
        }
    }
}

// ---------------- softmax over causal prefix + P split ----------------
__global__ __launch_bounds__(256)
void softmax_pconv()
{
    const int bi = blockIdx.x;
    const int r = bi & (SEQ - 1);
    const int z = bi >> 11;
    const int ncols = ((r >> 7) + 1) << 7;       // causal bound, tile-rounded
    const size_t rowbase = ((size_t)z * SEQ + r) * SEQ;
    const float* p = g_scores + rowbase;
    const int tid = threadIdx.x;
    __shared__ float red[256];

    const bool act = tid * 8 < ncols;
    float v[8];
    float mx = NEG_BIG;
    if (act) {
        float4 u0 = *(const float4*)(p + tid*8);
        float4 u1 = *(const float4*)(p + tid*8 + 4);
        v[0]=u0.x; v[1]=u0.y; v[2]=u0.z; v[3]=u0.w;
        v[4]=u1.x; v[5]=u1.y; v[6]=u1.z; v[7]=u1.w;
        #pragma unroll
        for (int i = 0; i < 8; i++) mx = fmaxf(mx, v[i]);
    }
    red[tid] = mx; __syncthreads();
    for (int off = 128; off > 0; off >>= 1) {
        if (tid < off) red[tid] = fmaxf(red[tid], red[tid + off]);
        __syncthreads();
    }
    mx = red[0]; __syncthreads();

    float sum = 0.f;
    if (act) {
        #pragma unroll
        for (int i = 0; i < 8; i++) { v[i] = expf(v[i] - mx); sum += v[i]; }
    }
    red[tid] = sum; __syncthreads();
    for (int off = 128; off > 0; off >>= 1) {
        if (tid < off) red[tid] += red[tid + off];
        __syncthreads();
    }
    float inv = 1.0f / red[0];

    if (act) {
        bf16* ph = g_phi + rowbase + tid*8;
        bf16* pl = g_plo + rowbase + tid*8;
        #pragma unroll
        for (int i = 0; i < 8; i += 2) {
            uint32_t hh, ll;
            split2(make_float2(v[i]*inv, v[i+1]*inv), hh, ll);
            *(uint32_t*)(ph + i) = hh;
            *(uint32_t*)(pl + i) = ll;
        }
    }
}

// ---------------- GEMM 3: attn = P @ V  (B = V^T, K over seq) ----------------
__global__ __launch_bounds__(256, 2)
void gemm_pv_tc()
{
    extern __shared__ uint8_t dsm[];
    uint32_t sm0 = s2u(dsm);
    const int z = blockIdx.y, b = z >> 4, h = z & 15;
    const int bm = blockIdx.x * 128;
    const int nc = (bm + 128) / 32;              // causal truncation
    float acc[4][4][4] = {};
    run_mma(sm0, g_phi + ((size_t)z * SEQ + bm) * SEQ, g_plo + ((size_t)z * SEQ + bm) * SEQ, SEQ,
                 g_vthi + (size_t)z * HD * SEQ,        g_vtlo + (size_t)z * HD * SEQ,        SEQ, nc, acc);
    const int lane = threadIdx.x & 31, warp = threadIdx.x >> 5;
    const int wr = warp >> 2, wc = warp & 3;
    const int g = lane >> 2, i2 = (lane & 3) * 2;
    #pragma unroll
    for (int mt = 0; mt < 4; mt++)
    #pragma unroll
    for (int nt = 0; nt < 4; nt++) {
        int r0 = bm + wr*64 + mt*16 + g;
        int cc = wc*32 + nt*8 + i2;
        #pragma unroll
        for (int half = 0; half < 2; half++) {
            int r = r0 + half * 8;
            size_t o = (size_t)(b * SEQ + r) * HID + h * HD + cc;
            uint32_t hh, ll;
            split2(make_float2(acc[mt][nt][half*2+0], acc[mt][nt][half*2+1]), hh, ll);
            *(uint32_t*)(g_ahi + o) = hh;
            *(uint32_t*)(g_alo + o) = ll;
        }
    }
}

// ---------------- GEMM 4: out = attn @ out_w^T + out_b ----------------
__global__ __launch_bounds__(256, 2)
void gemm_out_tc(const float* __restrict__ bias, float* __restrict__ outp)
{
    extern __shared__ uint8_t dsm[];
    uint32_t sm0 = s2u(dsm);
    const int bm = blockIdx.y * 128, bn = blockIdx.x * 128;
    float acc[4][4][4] = {};
    run_mma(sm0, g_ahi + (size_t)bm * HID, g_alo + (size_t)bm * HID, HID,
                 g_owhi + (size_t)bn * HID, g_owlo + (size_t)bn * HID, HID, HID/32, acc);
    const int lane = threadIdx.x & 31, warp = threadIdx.x >> 5;
    const int wr = warp >> 2, wc = warp & 3;
    const int g = lane >> 2, i2 = (lane & 3) * 2;
    #pragma unroll
    for (int mt = 0; mt < 4; mt++)
    #pragma unroll
    for (int nt = 0; nt < 4; nt++) {
        int r0 = bm + wr*64 + mt*16 + g;
        int cc = bn + wc*32 + nt*8 + i2;
        float2 v0 = make_float2(acc[mt][nt][0] + bias[cc], acc[mt][nt][1] + bias[cc+1]);
        float2 v1 = make_float2(acc[mt][nt][2] + bias[cc], acc[mt][nt][3] + bias[cc+1]);
        *(float2*)(outp + (size_t)r0 * HID + cc)     = v0;
        *(float2*)(outp + (size_t)(r0+8) * HID + cc) = v1;
    }
}

// ---------------------------------------------------------------------------
extern "C" void kernel_launch(void* const* d_in, const int* in_sizes, int n_in,
                              void* d_out, int out_size)
{
    (void)in_sizes; (void)n_in; (void)out_size;
    const int*   amask = (const int*)  d_in[1];
    const float* qkv_b = (const float*)d_in[3];
    const float* out_b = (const float*)d_in[5];
    float* outp = (float*)d_out;

    cudaFuncSetAttribute(gemm_qkv_tc,    cudaFuncAttributeMaxDynamicSharedMemorySize, DYN_SMEM);
    cudaFuncSetAttribute(gemm_scores_tc, cudaFuncAttributeMaxDynamicSharedMemorySize, DYN_SMEM);
    cudaFuncSetAttribute(gemm_pv_tc,     cudaFuncAttributeMaxDynamicSharedMemorySize, DYN_SMEM);
    cudaFuncSetAttribute(gemm_out_tc,    cudaFuncAttributeMaxDynamicSharedMemorySize, DYN_SMEM);

    conv_x <<<MTOK*HID/4/256, 256>>>((const float*)d_in[0]);
    conv_w <<<QKVN*HID/4/256, 256>>>((const float*)d_in[2]);
    conv_ow<<<HID*HID/4/256, 256>>>((const float*)d_in[4]);
    gemm_qkv_tc   <<<dim3(QKVN/128, MTOK/128), 256, DYN_SMEM>>>(qkv_b);
    rope_conv     <<<(2*NB*SEQ*NHEAD*64)/256, 256>>>();
    vtrans        <<<dim3(SEQ/32, HD/32, NBH), 256>>>();
    gemm_scores_tc<<<dim3(SEQ/128, SEQ/128, NBH), 256, DYN_SMEM>>>(amask);
    softmax_pconv <<<NBH*SEQ, 256>>>();
    gemm_pv_tc    <<<dim3(SEQ/128, NBH), 256, DYN_SMEM>>>();
    gemm_out_tc   <<<dim3(HID/128, MTOK/128), 256, DYN_SMEM>>>(out_b, outp);
}

// round 13
// speedup vs baseline: 2.2658x; 1.0161x over previous
#include <cuda_runtime.h>
#include <cuda_bf16.h>
#include <stdint.h>
#include <math.h>

#define NB    2
#define SEQ   2048
#define HID   2048
#define NHEAD 16
#define HD    128
#define NBH   (NB*NHEAD)     // 32
#define MTOK  (NB*SEQ)       // 4096
#define QKVN  (3*HID)        // 6144
#define NEG_BIG (-1e30f)
#define SM_SCALE 0.08838834764831845f

typedef __nv_bfloat16 bf16;

// ---------------- static device scratch ----------------
static __device__ float g_qkv   [(size_t)MTOK * QKVN];
static __device__ float g_scores[(size_t)NBH * SEQ * SEQ];
static __device__ bf16 g_xhi [(size_t)MTOK*HID],  g_xlo [(size_t)MTOK*HID];
static __device__ bf16 g_whi [(size_t)QKVN*HID],  g_wlo [(size_t)QKVN*HID];
static __device__ bf16 g_owhi[(size_t)HID*HID],   g_owlo[(size_t)HID*HID];
static __device__ bf16 g_qhi [(size_t)NBH*SEQ*HD], g_qlo [(size_t)NBH*SEQ*HD];
static __device__ bf16 g_khi [(size_t)NBH*SEQ*HD], g_klo [(size_t)NBH*SEQ*HD];
static __device__ bf16 g_vthi[(size_t)NBH*HD*SEQ], g_vtlo[(size_t)NBH*HD*SEQ];
static __device__ bf16 g_phi [(size_t)NBH*SEQ*SEQ], g_plo [(size_t)NBH*SEQ*SEQ];
static __device__ bf16 g_ahi [(size_t)MTOK*HID],  g_alo [(size_t)MTOK*HID];

// ---------------- helpers ----------------
__device__ __forceinline__ uint32_t s2u(const void* p) {
    uint32_t a;
    asm("{ .reg .u64 t; cvta.to.shared.u64 t, %1; cvt.u32.u64 %0, t; }" : "=r"(a) : "l"(p));
    return a;
}
__device__ __forceinline__ void cpa16(uint32_t sa, const void* g) {
    asm volatile("cp.async.cg.shared.global [%0], [%1], 16;" :: "r"(sa), "l"(g));
}
__device__ __forceinline__ void ldmx4(uint32_t (&r)[4], uint32_t a) {
    asm volatile("ldmatrix.sync.aligned.m8n8.x4.shared.b16 {%0,%1,%2,%3}, [%4];"
        : "=r"(r[0]), "=r"(r[1]), "=r"(r[2]), "=r"(r[3]) : "r"(a));
}
__device__ __forceinline__ void hmma(float (&d)[4], const uint32_t (&a)[4],
                                     uint32_t b0, uint32_t b1) {
    asm volatile("mma.sync.aligned.m16n8k16.row.col.f32.bf16.bf16.f32 "
        "{%0,%1,%2,%3}, {%4,%5,%6,%7}, {%8,%9}, {%0,%1,%2,%3};"
        : "+f"(d[0]), "+f"(d[1]), "+f"(d[2]), "+f"(d[3])
        : "r"(a[0]), "r"(a[1]), "r"(a[2]), "r"(a[3]), "r"(b0), "r"(b1));
}
__device__ __forceinline__ void split2(float2 v, uint32_t& hi, uint32_t& lo) {
    __nv_bfloat162 h = __float22bfloat162_rn(v);
    float2 hf = __bfloat1622float2(h);
    __nv_bfloat162 l = __float22bfloat162_rn(make_float2(v.x - hf.x, v.y - hf.y));
    hi = *reinterpret_cast<uint32_t*>(&h);
    lo = *reinterpret_cast<uint32_t*>(&l);
}

// SMEM: 2 stages, each 4 tiles of 128x32 bf16, row stride 80B (64B data + 16B pad)
#define LDSB32  80u
#define TILE32  (128u*LDSB32)     // 10240
#define OFF_AHI 0u
#define OFF_ALO TILE32
#define OFF_BHI (2u*TILE32)
#define OFF_BLO (3u*TILE32)
#define STAGE_B (4u*TILE32)       // 40960
#define DYN_SMEM (2*40960)        // 81920 -> 2 CTAs/SM

// Fill one 128x32-bf16 tile (2 cp.async of 16B per thread)
__device__ __forceinline__ void fillt32(uint32_t sbase, const bf16* __restrict__ src,
                                        size_t ld, int k0) {
    const int t = threadIdx.x;
    const int r = t >> 1, seg = t & 1;
    const char* g = (const char*)(src + (size_t)r * ld + (size_t)k0 + seg * 16);
    const uint32_t d = sbase + (uint32_t)r * LDSB32 + (uint32_t)seg * 32u;
    cpa16(d, g);
    cpa16(d + 16u, g + 16);
}

__device__ __forceinline__ void fill_stage(uint32_t sb,
        const bf16* Ahi, const bf16* Alo, size_t lda,
        const bf16* Bhi, const bf16* Blo, size_t ldb, int k0) {
    fillt32(sb + OFF_AHI, Ahi, lda, k0);
    fillt32(sb + OFF_ALO, Alo, lda, k0);
    fillt32(sb + OFF_BHI, Bhi, ldb, k0);
    fillt32(sb + OFF_BLO, Blo, ldb, k0);
    asm volatile("cp.async.commit_group;" ::: "memory");
}

// Double-buffered warp-fragment mainloop, ldmatrix loads, pass-major HMMA order
// (no back-to-back RAW on the same accumulator).
// acc += (Ahi+Alo) @ (Bhi+Blo)^T  (drop lo*lo). CTA 128x128, 8 warps 64x32 each.
__device__ void run_mma(uint32_t sm0,
        const bf16* __restrict__ Ahi, const bf16* __restrict__ Alo, size_t lda,
        const bf16* __restrict__ Bhi, const bf16* __restrict__ Blo, size_t ldb,
        int nc, float (&acc)[4][4][4])
{
    const int lane = threadIdx.x & 31, warp = threadIdx.x >> 5;
    const int wr = warp >> 2, wc = warp & 3;
    const int g8 = lane & 7, sel = lane >> 3;

    const uint32_t a_row = (uint32_t)(wr * 64 + (sel & 1) * 8 + g8);
    const uint32_t a_col = (uint32_t)((sel >> 1) * 16);
    const uint32_t b_row = (uint32_t)(wc * 32 + (sel >> 1) * 8 + g8);
    const uint32_t b_col = (uint32_t)((sel & 1) * 16);

    fill_stage(sm0, Ahi, Alo, lda, Bhi, Blo, ldb, 0);

    for (int c = 0; c < nc; c++) {
        const uint32_t sb = sm0 + (uint32_t)(c & 1) * STAGE_B;
        if (c + 1 < nc) {
            fill_stage(sm0 + (uint32_t)((c + 1) & 1) * STAGE_B,
                       Ahi, Alo, lda, Bhi, Blo, ldb, (c + 1) * 32);
            asm volatile("cp.async.wait_group 1;" ::: "memory");
        } else {
            asm volatile("cp.async.wait_group 0;" ::: "memory");
        }
        __syncthreads();

        #pragma unroll
        for (int ks = 0; ks < 2; ks++) {
            const uint32_t kb = (uint32_t)(ks * 32);
            uint32_t ahi[4][4], alo[4][4];
            #pragma unroll
            for (int mt = 0; mt < 4; mt++) {
                uint32_t ad = sb + (a_row + mt * 16) * LDSB32 + a_col + kb;
                ldmx4(ahi[mt], ad + OFF_AHI);
                ldmx4(alo[mt], ad + OFF_ALO);
            }
            #pragma unroll
            for (int ntp = 0; ntp < 2; ntp++) {
                uint32_t bd = sb + (b_row + ntp * 16) * LDSB32 + b_col + kb;
                uint32_t bhi[4], blo[4];
                ldmx4(bhi, bd + OFF_BHI);
                ldmx4(blo, bd + OFF_BLO);
                // pass 1: hi*hi — 8 distinct accumulators in sequence
                #pragma unroll
                for (int mt = 0; mt < 4; mt++) {
                    hmma(acc[mt][2*ntp],   ahi[mt], bhi[0], bhi[1]);
                    hmma(acc[mt][2*ntp+1], ahi[mt], bhi[2], bhi[3]);
                }
                // pass 2: lo*hi
                #pragma unroll
                for (int mt = 0; mt < 4; mt++) {
                    hmma(acc[mt][2*ntp],   alo[mt], bhi[0], bhi[1]);
                    hmma(acc[mt][2*ntp+1], alo[mt], bhi[2], bhi[3]);
                }
                // pass 3: hi*lo
                #pragma unroll
                for (int mt = 0; mt < 4; mt++) {
                    hmma(acc[mt][2*ntp],   ahi[mt], blo[0], blo[1]);
                    hmma(acc[mt][2*ntp+1], ahi[mt], blo[2], blo[3]);
                }
            }
        }
        __syncthreads();
    }
}

// ---------------- conversion kernels ----------------
__device__ __forceinline__ void conv_body(const float4* __restrict__ in,
                                          bf16* hi, bf16* lo, int n4) {
    int i = blockIdx.x * blockDim.x + threadIdx.x;
    if (i >= n4) return;
    float4 v = in[i];
    uint32_t h0, l0, h1, l1;
    split2(make_float2(v.x, v.y), h0, l0);
    split2(make_float2(v.z, v.w), h1, l1);
    *(uint2*)(hi + (size_t)i * 4) = make_uint2(h0, h1);
    *(uint2*)(lo + (size_t)i * 4) = make_uint2(l0, l1);
}
__global__ __launch_bounds__(256) void conv_x (const float* in) { conv_body((const float4*)in, g_xhi,  g_xlo,  MTOK*HID/4); }
__global__ __launch_bounds__(256) void conv_w (const float* in) { conv_body((const float4*)in, g_whi,  g_wlo,  QKVN*HID/4); }
__global__ __launch_bounds__(256) void conv_ow(const float* in) { conv_body((const float4*)in, g_owhi, g_owlo, HID*HID/4); }

// ---------------- GEMM 1: QKV projection ----------------
__global__ __launch_bounds__(256, 2)
void gemm_qkv_tc(const float* __restrict__ bias)
{
    extern __shared__ uint8_t dsm[];
    uint32_t sm0 = s2u(dsm);
    const int bm = blockIdx.y * 128, bn = blockIdx.x * 128;
    float acc[4][4][4] = {};
    run_mma(sm0, g_xhi + (size_t)bm * HID, g_xlo + (size_t)bm * HID, HID,
                 g_whi + (size_t)bn * HID, g_wlo + (size_t)bn * HID, HID, HID/32, acc);
    const int lane = threadIdx.x & 31, warp = threadIdx.x >> 5;
    const int wr = warp >> 2, wc = warp & 3;
    const int g = lane >> 2, i2 = (lane & 3) * 2;
    #pragma unroll
    for (int mt = 0; mt < 4; mt++)
    #pragma unroll
    for (int nt = 0; nt < 4; nt++) {
        int r0 = bm + wr*64 + mt*16 + g;
        int cc = bn + wc*32 + nt*8 + i2;
        float2 v0 = make_float2(acc[mt][nt][0] + bias[cc], acc[mt][nt][1] + bias[cc+1]);
        float2 v1 = make_float2(acc[mt][nt][2] + bias[cc], acc[mt][nt][3] + bias[cc+1]);
        *(float2*)(g_qkv + (size_t)r0 * QKVN + cc)       = v0;
        *(float2*)(g_qkv + (size_t)(r0+8) * QKVN + cc)   = v1;
    }
}

// ---------------- RoPE + q/k split ----------------
__global__ __launch_bounds__(256)
void rope_conv()
{
    int idx = blockIdx.x * 256 + threadIdx.x;
    const int i = idx & 63;  idx >>= 6;
    const int h = idx & 15;  idx >>= 4;
    const int s = idx & (SEQ - 1); idx >>= 11;
    const int b = idx & 1;
    const int which = idx >> 1;                 // 0=q, 1=k
    const size_t base = (size_t)(b * SEQ + s) * QKVN + which * HID + h * HD;
    // Reference: emb[d] = pos * f_{d mod 64}  (freqs concatenated twice)
    const int j0 = (2*i)     & 63;
    const int j1 = (2*i + 1) & 63;
    const float C = 0.20762050593045013f;       // log2(10000)/64
    float f0 = exp2f(-(float)j0 * C);
    float f1 = exp2f(-(float)j1 * C);
    float c0, s0, c1, s1;
    sincosf((float)s * f0, &s0, &c0);
    sincosf((float)s * f1, &s1, &c1);
    float x0 = g_qkv[base + 2*i];
    float x1 = g_qkv[base + 2*i + 1];
    float y0 = x0 * c0 - x1 * s0;
    float y1 = x1 * c1 + x0 * s1;
    const int z = b * NHEAD + h;
    const size_t o = ((size_t)z * SEQ + s) * HD + 2*i;
    uint32_t hh, ll;
    split2(make_float2(y0, y1), hh, ll);
    if (which == 0) { *(uint32_t*)(g_qhi + o) = hh; *(uint32_t*)(g_qlo + o) = ll; }
    else            { *(uint32_t*)(g_khi + o) = hh; *(uint32_t*)(g_klo + o) = ll; }
}

// ---------------- V transpose + split: [s,d] -> [d,s] ----------------
__global__ __launch_bounds__(256)
void vtrans()
{
    __shared__ float t[32][33];
    const int z = blockIdx.z, b = z >> 4, h = z & 15;
    const int s0 = blockIdx.x * 32, d0 = blockIdx.y * 32;
    const int tx = threadIdx.x & 31, ty = threadIdx.x >> 5;   // 32x8
    #pragma unroll
    for (int j = 0; j < 4; j++) {
        int s = s0 + ty + j * 8;
        t[ty + j*8][tx] = g_qkv[(size_t)(b * SEQ + s) * QKVN + 2*HID + h * HD + d0 + tx];
    }
    __syncthreads();
    #pragma unroll
    for (int j = 0; j < 4; j++) {
        int d = d0 + ty + j * 8;
        float val = t[tx][ty + j*8];
        bf16 hb = __float2bfloat16(val);
        size_t o = ((size_t)z * HD + d) * SEQ + s0 + tx;
        g_vthi[o] = hb;
        g_vtlo[o] = __float2bfloat16(val - __bfloat162float(hb));
    }
}

// ---------------- GEMM 2: scores (lower-tri tiles only) ----------------
__global__ __launch_bounds__(256, 2)
void gemm_scores_tc(const int* __restrict__ amask)
{
    if (blockIdx.x > blockIdx.y) return;
    extern __shared__ uint8_t dsm[];
    uint32_t sm0 = s2u(dsm);
    const int z = blockIdx.z, b = z >> 4;
    const int bm = blockIdx.y * 128, bn = blockIdx.x * 128;
    float acc[4][4][4] = {};
    run_mma(sm0, g_qhi + ((size_t)z * SEQ + bm) * HD, g_qlo + ((size_t)z * SEQ + bm) * HD, HD,
                 g_khi + ((size_t)z * SEQ + bn) * HD, g_klo + ((size_t)z * SEQ + bn) * HD, HD, HD/32, acc);
    const int lane = threadIdx.x & 31, warp = threadIdx.x >> 5;
    const int wr = warp >> 2, wc = warp & 3;
    const int g = lane >> 2, i2 = (lane & 3) * 2;
    const int* am = amask + b * SEQ;
    #pragma unroll
    for (int mt = 0; mt < 4; mt++)
    #pragma unroll
    for (int nt = 0; nt < 4; nt++) {
        int r0 = bm + wr*64 + mt*16 + g;
        int cc = bn + wc*32 + nt*8 + i2;
        float m0 = (am[cc]   != 0) ? 1.f : 0.f;
        float m1 = (am[cc+1] != 0) ? 1.f : 0.f;
        #pragma unroll
        for (int half = 0; half < 2; half++) {
            int r = r0 + half * 8;
            float v0 = acc[mt][nt][half*2+0] * SM_SCALE;
            float v1 = acc[mt][nt][half*2+1] * SM_SCALE;
            if (cc   > r || m0 == 0.f) v0 = NEG_BIG;
            if (cc+1 > r || m1 == 0.f) v1 = NEG_BIG;
            *(float2*)(g_scores + ((size_t)z * SEQ + r) * SEQ + cc) = make_float2(v0, v1);
        }
    }
}

// ---------------- softmax over causal prefix + P split ----------------
__global__ __launch_bounds__(256)
void softmax_pconv()
{
    const int bi = blockIdx.x;
    const int r = bi & (SEQ - 1);
    const int z = bi >> 11;
    const int ncols = ((r >> 7) + 1) << 7;       // causal bound, tile-rounded
    const size_t rowbase = ((size_t)z * SEQ + r) * SEQ;
    const float* p = g_scores + rowbase;
    const int tid = threadIdx.x;
    __shared__ float red[256];

    const bool act = tid * 8 < ncols;
    float v[8];
    float mx = NEG_BIG;
    if (act) {
        float4 u0 = *(const float4*)(p + tid*8);
        float4 u1 = *(const float4*)(p + tid*8 + 4);
        v[0]=u0.x; v[1]=u0.y; v[2]=u0.z; v[3]=u0.w;
        v[4]=u1.x; v[5]=u1.y; v[6]=u1.z; v[7]=u1.w;
        #pragma unroll
        for (int i = 0; i < 8; i++) mx = fmaxf(mx, v[i]);
    }
    red[tid] = mx; __syncthreads();
    for (int off = 128; off > 0; off >>= 1) {
        if (tid < off) red[tid] = fmaxf(red[tid], red[tid + off]);
        __syncthreads();
    }
    mx = red[0]; __syncthreads();

    float sum = 0.f;
    if (act) {
        #pragma unroll
        for (int i = 0; i < 8; i++) { v[i] = expf(v[i] - mx); sum += v[i]; }
    }
    red[tid] = sum; __syncthreads();
    for (int off = 128; off > 0; off >>= 1) {
        if (tid < off) red[tid] += red[tid + off];
        __syncthreads();
    }
    float inv = 1.0f / red[0];

    if (act) {
        bf16* ph = g_phi + rowbase + tid*8;
        bf16* pl = g_plo + rowbase + tid*8;
        #pragma unroll
        for (int i = 0; i < 8; i += 2) {
            uint32_t hh, ll;
            split2(make_float2(v[i]*inv, v[i+1]*inv), hh, ll);
            *(uint32_t*)(ph + i) = hh;
            *(uint32_t*)(pl + i) = ll;
        }
    }
}

// ---------------- GEMM 3: attn = P @ V  (B = V^T, K over seq) ----------------
__global__ __launch_bounds__(256, 2)
void gemm_pv_tc()
{
    extern __shared__ uint8_t dsm[];
    uint32_t sm0 = s2u(dsm);
    const int z = blockIdx.y, b = z >> 4, h = z & 15;
    const int bm = blockIdx.x * 128;
    const int nc = (bm + 128) / 32;              // causal truncation
    float acc[4][4][4] = {};
    run_mma(sm0, g_phi + ((size_t)z * SEQ + bm) * SEQ, g_plo + ((size_t)z * SEQ + bm) * SEQ, SEQ,
                 g_vthi + (size_t)z * HD * SEQ,        g_vtlo + (size_t)z * HD * SEQ,        SEQ, nc, acc);
    const int lane = threadIdx.x & 31, warp = threadIdx.x >> 5;
    const int wr = warp >> 2, wc = warp & 3;
    const int g = lane >> 2, i2 = (lane & 3) * 2;
    #pragma unroll
    for (int mt = 0; mt < 4; mt++)
    #pragma unroll
    for (int nt = 0; nt < 4; nt++) {
        int r0 = bm + wr*64 + mt*16 + g;
        int cc = wc*32 + nt*8 + i2;
        #pragma unroll
        for (int half = 0; half < 2; half++) {
            int r = r0 + half * 8;
            size_t o = (size_t)(b * SEQ + r) * HID + h * HD + cc;
            uint32_t hh, ll;
            split2(make_float2(acc[mt][nt][half*2+0], acc[mt][nt][half*2+1]), hh, ll);
            *(uint32_t*)(g_ahi + o) = hh;
            *(uint32_t*)(g_alo + o) = ll;
        }
    }
}

// ---------------- GEMM 4: out = attn @ out_w^T + out_b ----------------
__global__ __launch_bounds__(256, 2)
void gemm_out_tc(const float* __restrict__ bias, float* __restrict__ outp)
{
    extern __shared__ uint8_t dsm[];
    uint32_t sm0 = s2u(dsm);
    const int bm = blockIdx.y * 128, bn = blockIdx.x * 128;
    float acc[4][4][4] = {};
    run_mma(sm0, g_ahi + (size_t)bm * HID, g_alo + (size_t)bm * HID, HID,
                 g_owhi + (size_t)bn * HID, g_owlo + (size_t)bn * HID, HID, HID/32, acc);
    const int lane = threadIdx.x & 31, warp = threadIdx.x >> 5;
    const int wr = warp >> 2, wc = warp & 3;
    const int g = lane >> 2, i2 = (lane & 3) * 2;
    #pragma unroll
    for (int mt = 0; mt < 4; mt++)
    #pragma unroll
    for (int nt = 0; nt < 4; nt++) {
        int r0 = bm + wr*64 + mt*16 + g;
        int cc = bn + wc*32 + nt*8 + i2;
        float2 v0 = make_float2(acc[mt][nt][0] + bias[cc], acc[mt][nt][1] + bias[cc+1]);
        float2 v1 = make_float2(acc[mt][nt][2] + bias[cc], acc[mt][nt][3] + bias[cc+1]);
        *(float2*)(outp + (size_t)r0 * HID + cc)     = v0;
        *(float2*)(outp + (size_t)(r0+8) * HID + cc) = v1;
    }
}

// ---------------------------------------------------------------------------
extern "C" void kernel_launch(void* const* d_in, const int* in_sizes, int n_in,
                              void* d_out, int out_size)
{
    (void)in_sizes; (void)n_in; (void)out_size;
    const int*   amask = (const int*)  d_in[1];
    const float* qkv_b = (const float*)d_in[3];
    const float* out_b = (const float*)d_in[5];
    float* outp = (float*)d_out;

    cudaFuncSetAttribute(gemm_qkv_tc,    cudaFuncAttributeMaxDynamicSharedMemorySize, DYN_SMEM);
    cudaFuncSetAttribute(gemm_scores_tc, cudaFuncAttributeMaxDynamicSharedMemorySize, DYN_SMEM);
    cudaFuncSetAttribute(gemm_pv_tc,     cudaFuncAttributeMaxDynamicSharedMemorySize, DYN_SMEM);
    cudaFuncSetAttribute(gemm_out_tc,    cudaFuncAttributeMaxDynamicSharedMemorySize, DYN_SMEM);

    conv_x <<<MTOK*HID/4/256, 256>>>((const float*)d_in[0]);
    conv_w <<<QKVN*HID/4/256, 256>>>((const float*)d_in[2]);
    conv_ow<<<HID*HID/4/256, 256>>>((const float*)d_in[4]);
    gemm_qkv_tc   <<<dim3(QKVN/128, MTOK/128), 256, DYN_SMEM>>>(qkv_b);
    rope_conv     <<<(2*NB*SEQ*NHEAD*64)/256, 256>>>();
    vtrans        <<<dim3(SEQ/32, HD/32, NBH), 256>>>();
    gemm_scores_tc<<<dim3(SEQ/128, SEQ/128, NBH), 256, DYN_SMEM>>>(amask);
    softmax_pconv <<<NBH*SEQ, 256>>>();
    gemm_pv_tc    <<<dim3(SEQ/128, NBH), 256, DYN_SMEM>>>();
    gemm_out_tc   <<<dim3(HID/128, MTOK/128), 256, DYN_SMEM>>>(out_b, outp);
}

// round 15
// speedup vs baseline: 2.2878x; 1.0097x over previous
#include <cuda_runtime.h>
#include <cuda_bf16.h>
#include <stdint.h>
#include <math.h>

#define NB    2
#define SEQ   2048
#define HID   2048
#define NHEAD 16
#define HD    128
#define NBH   (NB*NHEAD)     // 32
#define MTOK  (NB*SEQ)       // 4096
#define QKVN  (3*HID)        // 6144
#define NEG_BIG (-1e30f)
#define SM_SCALE 0.08838834764831845f
#define ROPE_C 0.20762050593045013f     // log2(10000)/64

typedef __nv_bfloat16 bf16;

// ---------------- static device scratch ----------------
static __device__ float g_qkv   [(size_t)MTOK * QKVN];   // only v region used now
static __device__ float g_scores[(size_t)NBH * SEQ * SEQ];
static __device__ bf16 g_xhi [(size_t)MTOK*HID],  g_xlo [(size_t)MTOK*HID];
static __device__ bf16 g_whi [(size_t)QKVN*HID],  g_wlo [(size_t)QKVN*HID];
static __device__ bf16 g_owhi[(size_t)HID*HID],   g_owlo[(size_t)HID*HID];
static __device__ bf16 g_qhi [(size_t)NBH*SEQ*HD], g_qlo [(size_t)NBH*SEQ*HD];
static __device__ bf16 g_khi [(size_t)NBH*SEQ*HD], g_klo [(size_t)NBH*SEQ*HD];
static __device__ bf16 g_vthi[(size_t)NBH*HD*SEQ], g_vtlo[(size_t)NBH*HD*SEQ];
static __device__ bf16 g_phi [(size_t)NBH*SEQ*SEQ], g_plo [(size_t)NBH*SEQ*SEQ];
static __device__ bf16 g_ahi [(size_t)MTOK*HID],  g_alo [(size_t)MTOK*HID];

// ---------------- helpers ----------------
__device__ __forceinline__ uint32_t s2u(const void* p) {
    uint32_t a;
    asm("{ .reg .u64 t; cvta.to.shared.u64 t, %1; cvt.u32.u64 %0, t; }" : "=r"(a) : "l"(p));
    return a;
}
__device__ __forceinline__ void cpa16(uint32_t sa, const void* g) {
    asm volatile("cp.async.cg.shared.global [%0], [%1], 16;" :: "r"(sa), "l"(g));
}
__device__ __forceinline__ void ldmx4(uint32_t (&r)[4], uint32_t a) {
    asm volatile("ldmatrix.sync.aligned.m8n8.x4.shared.b16 {%0,%1,%2,%3}, [%4];"
        : "=r"(r[0]), "=r"(r[1]), "=r"(r[2]), "=r"(r[3]) : "r"(a));
}
__device__ __forceinline__ void hmma(float (&d)[4], const uint32_t (&a)[4],
                                     uint32_t b0, uint32_t b1) {
    asm volatile("mma.sync.aligned.m16n8k16.row.col.f32.bf16.bf16.f32 "
        "{%0,%1,%2,%3}, {%4,%5,%6,%7}, {%8,%9}, {%0,%1,%2,%3};"
        : "+f"(d[0]), "+f"(d[1]), "+f"(d[2]), "+f"(d[3])
        : "r"(a[0]), "r"(a[1]), "r"(a[2]), "r"(a[3]), "r"(b0), "r"(b1));
}
__device__ __forceinline__ void split2(float2 v, uint32_t& hi, uint32_t& lo) {
    __nv_bfloat162 h = __float22bfloat162_rn(v);
    float2 hf = __bfloat1622float2(h);
    __nv_bfloat162 l = __float22bfloat162_rn(make_float2(v.x - hf.x, v.y - hf.y));
    hi = *reinterpret_cast<uint32_t*>(&h);
    lo = *reinterpret_cast<uint32_t*>(&l);
}

// SMEM: 2 stages, each 4 tiles of 128x32 bf16, row stride 80B
#define LDSB32  80u
#define TILE32  (128u*LDSB32)
#define OFF_AHI 0u
#define OFF_ALO TILE32
#define OFF_BHI (2u*TILE32)
#define OFF_BLO (3u*TILE32)
#define STAGE_B (4u*TILE32)       // 40960
#define DYN_SMEM (2*40960)        // 81920 -> 2 CTAs/SM

__device__ __forceinline__ void fillt32(uint32_t sbase, const bf16* __restrict__ src,
                                        size_t ld, int k0) {
    const int t = threadIdx.x;
    const int r = t >> 1, seg = t & 1;
    const char* g = (const char*)(src + (size_t)r * ld + (size_t)k0 + seg * 16);
    const uint32_t d = sbase + (uint32_t)r * LDSB32 + (uint32_t)seg * 32u;
    cpa16(d, g);
    cpa16(d + 16u, g + 16);
}
__device__ __forceinline__ void fill_stage(uint32_t sb,
        const bf16* Ahi, const bf16* Alo, size_t lda,
        const bf16* Bhi, const bf16* Blo, size_t ldb, int k0) {
    fillt32(sb + OFF_AHI, Ahi, lda, k0);
    fillt32(sb + OFF_ALO, Alo, lda, k0);
    fillt32(sb + OFF_BHI, Bhi, ldb, k0);
    fillt32(sb + OFF_BLO, Blo, ldb, k0);
    asm volatile("cp.async.commit_group;" ::: "memory");
}

// Double-buffered warp-fragment mainloop (pass-major HMMA order).
__device__ void run_mma(uint32_t sm0,
        const bf16* __restrict__ Ahi, const bf16* __restrict__ Alo, size_t lda,
        const bf16* __restrict__ Bhi, const bf16* __restrict__ Blo, size_t ldb,
        int nc, float (&acc)[4][4][4])
{
    const int lane = threadIdx.x & 31, warp = threadIdx.x >> 5;
    const int wr = warp >> 2, wc = warp & 3;
    const int g8 = lane & 7, sel = lane >> 3;

    const uint32_t a_row = (uint32_t)(wr * 64 + (sel & 1) * 8 + g8);
    const uint32_t a_col = (uint32_t)((sel >> 1) * 16);
    const uint32_t b_row = (uint32_t)(wc * 32 + (sel >> 1) * 8 + g8);
    const uint32_t b_col = (uint32_t)((sel & 1) * 16);

    fill_stage(sm0, Ahi, Alo, lda, Bhi, Blo, ldb, 0);

    for (int c = 0; c < nc; c++) {
        const uint32_t sb = sm0 + (uint32_t)(c & 1) * STAGE_B;
        if (c + 1 < nc) {
            fill_stage(sm0 + (uint32_t)((c + 1) & 1) * STAGE_B,
                       Ahi, Alo, lda, Bhi, Blo, ldb, (c + 1) * 32);
            asm volatile("cp.async.wait_group 1;" ::: "memory");
        } else {
            asm volatile("cp.async.wait_group 0;" ::: "memory");
        }
        __syncthreads();

        #pragma unroll
        for (int ks = 0; ks < 2; ks++) {
            const uint32_t kb = (uint32_t)(ks * 32);
            uint32_t ahi[4][4], alo[4][4];
            #pragma unroll
            for (int mt = 0; mt < 4; mt++) {
                uint32_t ad = sb + (a_row + mt * 16) * LDSB32 + a_col + kb;
                ldmx4(ahi[mt], ad + OFF_AHI);
                ldmx4(alo[mt], ad + OFF_ALO);
            }
            #pragma unroll
            for (int ntp = 0; ntp < 2; ntp++) {
                uint32_t bd = sb + (b_row + ntp * 16) * LDSB32 + b_col + kb;
                uint32_t bhi[4], blo[4];
                ldmx4(bhi, bd + OFF_BHI);
                ldmx4(blo, bd + OFF_BLO);
                #pragma unroll
                for (int mt = 0; mt < 4; mt++) {
                    hmma(acc[mt][2*ntp],   ahi[mt], bhi[0], bhi[1]);
                    hmma(acc[mt][2*ntp+1], ahi[mt], bhi[2], bhi[3]);
                }
                #pragma unroll
                for (int mt = 0; mt < 4; mt++) {
                    hmma(acc[mt][2*ntp],   alo[mt], bhi[0], bhi[1]);
                    hmma(acc[mt][2*ntp+1], alo[mt], bhi[2], bhi[3]);
                }
                #pragma unroll
                for (int mt = 0; mt < 4; mt++) {
                    hmma(acc[mt][2*ntp],   ahi[mt], blo[0], blo[1]);
                    hmma(acc[mt][2*ntp+1], ahi[mt], blo[2], blo[3]);
                }
            }
        }
        __syncthreads();
    }
}

// ---------------- fused conversion kernel (x, qkv_w, out_w) ----------------
#define N4_X  (MTOK*HID/4)
#define N4_W  (QKVN*HID/4)
#define N4_OW (HID*HID/4)
__global__ __launch_bounds__(256)
void conv_all(const float* __restrict__ x, const float* __restrict__ w,
              const float* __restrict__ ow)
{
    int i = blockIdx.x * blockDim.x + threadIdx.x;
    const float4* in; bf16 *hi, *lo; int base;
    if (i < N4_X)            { in = (const float4*)x;  hi = g_xhi;  lo = g_xlo;  base = 0; }
    else if (i < N4_X+N4_W)  { in = (const float4*)w;  hi = g_whi;  lo = g_wlo;  base = N4_X; }
    else if (i < N4_X+N4_W+N4_OW) { in = (const float4*)ow; hi = g_owhi; lo = g_owlo; base = N4_X+N4_W; }
    else return;
    i -= base;
    float4 v = in[i];
    uint32_t h0, l0, h1, l1;
    split2(make_float2(v.x, v.y), h0, l0);
    split2(make_float2(v.z, v.w), h1, l1);
    *(uint2*)(hi + (size_t)i * 4) = make_uint2(h0, h1);
    *(uint2*)(lo + (size_t)i * 4) = make_uint2(l0, l1);
}

// ---------------- GEMM 1: QKV projection, RoPE+split fused in epilogue ----------------
__global__ __launch_bounds__(256, 2)
void gemm_qkv_tc(const float* __restrict__ bias)
{
    extern __shared__ uint8_t dsm[];
    uint32_t sm0 = s2u(dsm);
    const int bm = blockIdx.y * 128, bn = blockIdx.x * 128;
    float acc[4][4][4] = {};
    run_mma(sm0, g_xhi + (size_t)bm * HID, g_xlo + (size_t)bm * HID, HID,
                 g_whi + (size_t)bn * HID, g_wlo + (size_t)bn * HID, HID, HID/32, acc);
    const int lane = threadIdx.x & 31, warp = threadIdx.x >> 5;
    const int wr = warp >> 2, wc = warp & 3;
    const int g = lane >> 2, i2 = (lane & 3) * 2;
    const int which = bn >> 11;                 // uniform per CTA: 0=q,1=k,2=v

    if (which < 2) {
        // RoPE + hi/lo split, write directly to per-head q/k layout
        bf16* dhi = (which == 0) ? g_qhi : g_khi;
        bf16* dlo = (which == 0) ? g_qlo : g_klo;
        #pragma unroll
        for (int mt = 0; mt < 4; mt++)
        #pragma unroll
        for (int nt = 0; nt < 4; nt++) {
            int r0 = bm + wr*64 + mt*16 + g;
            int cc = bn + wc*32 + nt*8 + i2;
            int within = cc & 2047;
            int h = within >> 7, d = within & 127;
            int j0 = d & 63;                    // d even -> j1 = j0+1
            float f0 = exp2f(-(float)j0 * ROPE_C);
            float f1 = exp2f(-(float)(j0 + 1) * ROPE_C);
            float b0v = bias[cc], b1v = bias[cc+1];
            #pragma unroll
            for (int half = 0; half < 2; half++) {
                int r = r0 + half * 8;
                int b = r >> 11, s = r & (SEQ - 1);
                float x0 = acc[mt][nt][half*2+0] + b0v;
                float x1 = acc[mt][nt][half*2+1] + b1v;
                float c0, s0, c1, s1;
                sincosf((float)s * f0, &s0, &c0);
                sincosf((float)s * f1, &s1, &c1);
                float y0 = x0 * c0 - x1 * s0;
                float y1 = x1 * c1 + x0 * s1;
                int z = b * NHEAD + h;
                size_t o = ((size_t)z * SEQ + s) * HD + d;
                uint32_t hh, ll;
                split2(make_float2(y0, y1), hh, ll);
                *(uint32_t*)(dhi + o) = hh;
                *(uint32_t*)(dlo + o) = ll;
            }
        }
    } else {
        // v region: plain fp32 write (vtrans consumes it)
        #pragma unroll
        for (int mt = 0; mt < 4; mt++)
        #pragma unroll
        for (int nt = 0; nt < 4; nt++) {
            int r0 = bm + wr*64 + mt*16 + g;
            int cc = bn + wc*32 + nt*8 + i2;
            float2 v0 = make_float2(acc[mt][nt][0] + bias[cc], acc[mt][nt][1] + bias[cc+1]);
            float2 v1 = make_float2(acc[mt][nt][2] + bias[cc], acc[mt][nt][3] + bias[cc+1]);
            *(float2*)(g_qkv + (size_t)r0 * QKVN + cc)     = v0;
            *(float2*)(g_qkv + (size_t)(r0+8) * QKVN + cc) = v1;
        }
    }
}

// ---------------- V transpose + split: [s,d] -> [d,s] ----------------
__global__ __launch_bounds__(256)
void vtrans()
{
    __shared__ float t[32][33];
    const int z = blockIdx.z, b = z >> 4, h = z & 15;
    const int s0 = blockIdx.x * 32, d0 = blockIdx.y * 32;
    const int tx = threadIdx.x & 31, ty = threadIdx.x >> 5;
    #pragma unroll
    for (int j = 0; j < 4; j++) {
        int s = s0 + ty + j * 8;
        t[ty + j*8][tx] = g_qkv[(size_t)(b * SEQ + s) * QKVN + 2*HID + h * HD + d0 + tx];
    }
    __syncthreads();
    #pragma unroll
    for (int j = 0; j < 4; j++) {
        int d = d0 + ty + j * 8;
        float val = t[tx][ty + j*8];
        bf16 hb = __float2bfloat16(val);
        size_t o = ((size_t)z * HD + d) * SEQ + s0 + tx;
        g_vthi[o] = hb;
        g_vtlo[o] = __float2bfloat16(val - __bfloat162float(hb));
    }
}

// ---------------- GEMM 2: scores — compact lower-tri grid (136 tiles) ----------------
__global__ __launch_bounds__(256, 2)
void gemm_scores_tc(const int* __restrict__ amask)
{
    extern __shared__ uint8_t dsm[];
    uint32_t sm0 = s2u(dsm);
    const int t = blockIdx.x;                    // 0..135 -> (bm_t, bn_t), bn<=bm
    int bmt = (int)((sqrtf(8.0f * (float)t + 1.0f) - 1.0f) * 0.5f);
    while ((bmt + 1) * (bmt + 2) / 2 <= t) bmt++;
    while (bmt * (bmt + 1) / 2 > t) bmt--;
    const int bnt = t - bmt * (bmt + 1) / 2;
    const int z = blockIdx.y, b = z >> 4;
    const int bm = bmt * 128, bn = bnt * 128;

    float acc[4][4][4] = {};
    run_mma(sm0, g_qhi + ((size_t)z * SEQ + bm) * HD, g_qlo + ((size_t)z * SEQ + bm) * HD, HD,
                 g_khi + ((size_t)z * SEQ + bn) * HD, g_klo + ((size_t)z * SEQ + bn) * HD, HD, HD/32, acc);
    const int lane = threadIdx.x & 31, warp = threadIdx.x >> 5;
    const int wr = warp >> 2, wc = warp & 3;
    const int g = lane >> 2, i2 = (lane & 3) * 2;
    const int* am = amask + b * SEQ;
    #pragma unroll
    for (int mt = 0; mt < 4; mt++)
    #pragma unroll
    for (int nt = 0; nt < 4; nt++) {
        int r0 = bm + wr*64 + mt*16 + g;
        int cc = bn + wc*32 + nt*8 + i2;
        float m0 = (am[cc]   != 0) ? 1.f : 0.f;
        float m1 = (am[cc+1] != 0) ? 1.f : 0.f;
        #pragma unroll
        for (int half = 0; half < 2; half++) {
            int r = r0 + half * 8;
            float v0 = acc[mt][nt][half*2+0] * SM_SCALE;
            float v1 = acc[mt][nt][half*2+1] * SM_SCALE;
            if (cc   > r || m0 == 0.f) v0 = NEG_BIG;
            if (cc+1 > r || m1 == 0.f) v1 = NEG_BIG;
            *(float2*)(g_scores + ((size_t)z * SEQ + r) * SEQ + cc) = make_float2(v0, v1);
        }
    }
}

// ---------------- softmax over causal prefix + P split ----------------
__global__ __launch_bounds__(256)
void softmax_pconv()
{
    const int bi = blockIdx.x;
    const int r = bi & (SEQ - 1);
    const int z = bi >> 11;
    const int ncols = ((r >> 7) + 1) << 7;
    const size_t rowbase = ((size_t)z * SEQ + r) * SEQ;
    const float* p = g_scores + rowbase;
    const int tid = threadIdx.x;
    __shared__ float red[256];

    const bool act = tid * 8 < ncols;
    float v[8];
    float mx = NEG_BIG;
    if (act) {
        float4 u0 = *(const float4*)(p + tid*8);
        float4 u1 = *(const float4*)(p + tid*8 + 4);
        v[0]=u0.x; v[1]=u0.y; v[2]=u0.z; v[3]=u0.w;
        v[4]=u1.x; v[5]=u1.y; v[6]=u1.z; v[7]=u1.w;
        #pragma unroll
        for (int i = 0; i < 8; i++) mx = fmaxf(mx, v[i]);
    }
    red[tid] = mx; __syncthreads();
    for (int off = 128; off > 0; off >>= 1) {
        if (tid < off) red[tid] = fmaxf(red[tid], red[tid + off]);
        __syncthreads();
    }
    mx = red[0]; __syncthreads();

    float sum = 0.f;
    if (act) {
        #pragma unroll
        for (int i = 0; i < 8; i++) { v[i] = expf(v[i] - mx); sum += v[i]; }
    }
    red[tid] = sum; __syncthreads();
    for (int off = 128; off > 0; off >>= 1) {
        if (tid < off) red[tid] += red[tid + off];
        __syncthreads();
    }
    float inv = 1.0f / red[0];

    if (act) {
        bf16* ph = g_phi + rowbase + tid*8;
        bf16* pl = g_plo + rowbase + tid*8;
        #pragma unroll
        for (int i = 0; i < 8; i += 2) {
            uint32_t hh, ll;
            split2(make_float2(v[i]*inv, v[i+1]*inv), hh, ll);
            *(uint32_t*)(ph + i) = hh;
            *(uint32_t*)(pl + i) = ll;
        }
    }
}

// ---------------- GEMM 3: attn = P @ V, LPT order (heavy bm first) ----------------
__global__ __launch_bounds__(256, 2)
void gemm_pv_tc()
{
    extern __shared__ uint8_t dsm[];
    uint32_t sm0 = s2u(dsm);
    const int z = blockIdx.y, b = z >> 4, h = z & 15;
    const int bm = (gridDim.x - 1 - blockIdx.x) * 128;   // reversed: longest K-loops first
    const int nc = (bm + 128) / 32;
    float acc[4][4][4] = {};
    run_mma(sm0, g_phi + ((size_t)z * SEQ + bm) * SEQ, g_plo + ((size_t)z * SEQ + bm) * SEQ, SEQ,
                 g_vthi + (size_t)z * HD * SEQ,        g_vtlo + (size_t)z * HD * SEQ,        SEQ, nc, acc);
    const int lane = threadIdx.x & 31, warp = threadIdx.x >> 5;
    const int wr = warp >> 2, wc = warp & 3;
    const int g = lane >> 2, i2 = (lane & 3) * 2;
    #pragma unroll
    for (int mt = 0; mt < 4; mt++)
    #pragma unroll
    for (int nt = 0; nt < 4; nt++) {
        int r0 = bm + wr*64 + mt*16 + g;
        int cc = wc*32 + nt*8 + i2;
        #pragma unroll
        for (int half = 0; half < 2; half++) {
            int r = r0 + half * 8;
            size_t o = (size_t)(b * SEQ + r) * HID + h * HD + cc;
            uint32_t hh, ll;
            split2(make_float2(acc[mt][nt][half*2+0], acc[mt][nt][half*2+1]), hh, ll);
            *(uint32_t*)(g_ahi + o) = hh;
            *(uint32_t*)(g_alo + o) = ll;
        }
    }
}

// ---------------- GEMM 4: out = attn @ out_w^T + out_b ----------------
__global__ __launch_bounds__(256, 2)
void gemm_out_tc(const float* __restrict__ bias, float* __restrict__ outp)
{
    extern __shared__ uint8_t dsm[];
    uint32_t sm0 = s2u(dsm);
    const int bm = blockIdx.y * 128, bn = blockIdx.x * 128;
    float acc[4][4][4] = {};
    run_mma(sm0, g_ahi + (size_t)bm * HID, g_alo + (size_t)bm * HID, HID,
                 g_owhi + (size_t)bn * HID, g_owlo + (size_t)bn * HID, HID, HID/32, acc);
    const int lane = threadIdx.x & 31, warp = threadIdx.x >> 5;
    const int wr = warp >> 2, wc = warp & 3;
    const int g = lane >> 2, i2 = (lane & 3) * 2;
    #pragma unroll
    for (int mt = 0; mt < 4; mt++)
    #pragma unroll
    for (int nt = 0; nt < 4; nt++) {
        int r0 = bm + wr*64 + mt*16 + g;
        int cc = bn + wc*32 + nt*8 + i2;
        float2 v0 = make_float2(acc[mt][nt][0] + bias[cc], acc[mt][nt][1] + bias[cc+1]);
        float2 v1 = make_float2(acc[mt][nt][2] + bias[cc], acc[mt][nt][3] + bias[cc+1]);
        *(float2*)(outp + (size_t)r0 * HID + cc)     = v0;
        *(float2*)(outp + (size_t)(r0+8) * HID + cc) = v1;
    }
}

// ---------------------------------------------------------------------------
extern "C" void kernel_launch(void* const* d_in, const int* in_sizes, int n_in,
                              void* d_out, int out_size)
{
    (void)in_sizes; (void)n_in; (void)out_size;
    const int*   amask = (const int*)  d_in[1];
    const float* qkv_b = (const float*)d_in[3];
    const float* out_b = (const float*)d_in[5];
    float* outp = (float*)d_out;

    cudaFuncSetAttribute(gemm_qkv_tc,    cudaFuncAttributeMaxDynamicSharedMemorySize, DYN_SMEM);
    cudaFuncSetAttribute(gemm_scores_tc, cudaFuncAttributeMaxDynamicSharedMemorySize, DYN_SMEM);
    cudaFuncSetAttribute(gemm_pv_tc,     cudaFuncAttributeMaxDynamicSharedMemorySize, DYN_SMEM);
    cudaFuncSetAttribute(gemm_out_tc,    cudaFuncAttributeMaxDynamicSharedMemorySize, DYN_SMEM);

    const int conv_blocks = (N4_X + N4_W + N4_OW + 255) / 256;
    conv_all<<<conv_blocks, 256>>>((const float*)d_in[0], (const float*)d_in[2],
                                   (const float*)d_in[4]);
    gemm_qkv_tc   <<<dim3(QKVN/128, MTOK/128), 256, DYN_SMEM>>>(qkv_b);
    vtrans        <<<dim3(SEQ/32, HD/32, NBH), 256>>>();
    gemm_scores_tc<<<dim3(136, NBH), 256, DYN_SMEM>>>(amask);
    softmax_pconv <<<NBH*SEQ, 256>>>();
    gemm_pv_tc    <<<dim3(SEQ/128, NBH), 256, DYN_SMEM>>>();
    gemm_out_tc   <<<dim3(HID/128, MTOK/128), 256, DYN_SMEM>>>(out_b, outp);
}

// round 16
// speedup vs baseline: 2.9931x; 1.3083x over previous
#include <cuda_runtime.h>
#include <cuda_fp16.h>
#include <stdint.h>
#include <math.h>

#define NB    2
#define SEQ   2048
#define HID   2048
#define NHEAD 16
#define HD    128
#define NBH   (NB*NHEAD)     // 32
#define MTOK  (NB*SEQ)       // 4096
#define QKVN  (3*HID)        // 6144
#define NEG_BIG (-1e30f)
#define SM_SCALE 0.08838834764831845f
#define ROPE_C 0.20762050593045013f     // log2(10000)/64

typedef __half h16;

// ---------------- static device scratch ----------------
static __device__ float g_qkv   [(size_t)MTOK * QKVN];   // v region used
static __device__ float g_scores[(size_t)NBH * SEQ * SEQ];
static __device__ h16 g_xhi [(size_t)MTOK*HID],  g_xlo [(size_t)MTOK*HID];
static __device__ h16 g_w   [(size_t)QKVN*HID];          // single fp16 (B side)
static __device__ h16 g_ow  [(size_t)HID*HID];           // single fp16
static __device__ h16 g_qhi [(size_t)NBH*SEQ*HD], g_qlo [(size_t)NBH*SEQ*HD];
static __device__ h16 g_k   [(size_t)NBH*SEQ*HD];        // single fp16
static __device__ h16 g_vt  [(size_t)NBH*HD*SEQ];        // single fp16, [d][s]
static __device__ h16 g_phi [(size_t)NBH*SEQ*SEQ], g_plo [(size_t)NBH*SEQ*SEQ];
static __device__ h16 g_ahi [(size_t)MTOK*HID],  g_alo [(size_t)MTOK*HID];

// ---------------- helpers ----------------
__device__ __forceinline__ uint32_t s2u(const void* p) {
    uint32_t a;
    asm("{ .reg .u64 t; cvta.to.shared.u64 t, %1; cvt.u32.u64 %0, t; }" : "=r"(a) : "l"(p));
    return a;
}
__device__ __forceinline__ void cpa16(uint32_t sa, const void* g) {
    asm volatile("cp.async.cg.shared.global [%0], [%1], 16;" :: "r"(sa), "l"(g));
}
__device__ __forceinline__ void ldmx4(uint32_t (&r)[4], uint32_t a) {
    asm volatile("ldmatrix.sync.aligned.m8n8.x4.shared.b16 {%0,%1,%2,%3}, [%4];"
        : "=r"(r[0]), "=r"(r[1]), "=r"(r[2]), "=r"(r[3]) : "r"(a));
}
__device__ __forceinline__ void hmma(float (&d)[4], const uint32_t (&a)[4],
                                     uint32_t b0, uint32_t b1) {
    asm volatile("mma.sync.aligned.m16n8k16.row.col.f32.f16.f16.f32 "
        "{%0,%1,%2,%3}, {%4,%5,%6,%7}, {%8,%9}, {%0,%1,%2,%3};"
        : "+f"(d[0]), "+f"(d[1]), "+f"(d[2]), "+f"(d[3])
        : "r"(a[0]), "r"(a[1]), "r"(a[2]), "r"(a[3]), "r"(b0), "r"(b1));
}
// fp16 hi/lo split of a float pair
__device__ __forceinline__ void split2(float2 v, uint32_t& hi, uint32_t& lo) {
    __half2 h = __float22half2_rn(v);
    float2 hf = __half22float2(h);
    __half2 l = __float22half2_rn(make_float2(v.x - hf.x, v.y - hf.y));
    hi = *reinterpret_cast<uint32_t*>(&h);
    lo = *reinterpret_cast<uint32_t*>(&l);
}
__device__ __forceinline__ uint32_t pack2(float2 v) {
    __half2 h = __float22half2_rn(v);
    return *reinterpret_cast<uint32_t*>(&h);
}

// SMEM: 2 stages, each 3 tiles (Ahi, Alo, B) of 128x32 fp16, row stride 80B
#define LDSB32  80u
#define TILE32  (128u*LDSB32)     // 10240
#define OFF_AHI 0u
#define OFF_ALO TILE32
#define OFF_B   (2u*TILE32)
#define STAGE_B (3u*TILE32)       // 30720
#define DYN_SMEM (2*30720)        // 61440 -> 2 CTAs/SM

__device__ __forceinline__ void fillt32(uint32_t sbase, const h16* __restrict__ src,
                                        size_t ld, int k0) {
    const int t = threadIdx.x;
    const int r = t >> 1, seg = t & 1;
    const char* g = (const char*)(src + (size_t)r * ld + (size_t)k0 + seg * 16);
    const uint32_t d = sbase + (uint32_t)r * LDSB32 + (uint32_t)seg * 32u;
    cpa16(d, g);
    cpa16(d + 16u, g + 16);
}
__device__ __forceinline__ void fill_stage(uint32_t sb,
        const h16* Ahi, const h16* Alo, size_t lda,
        const h16* B, size_t ldb, int k0) {
    fillt32(sb + OFF_AHI, Ahi, lda, k0);
    fillt32(sb + OFF_ALO, Alo, lda, k0);
    fillt32(sb + OFF_B,   B,   ldb, k0);
    asm volatile("cp.async.commit_group;" ::: "memory");
}

// Double-buffered warp-fragment mainloop, 2-pass fp16:
// acc += (Ahi+Alo) @ B^T   (A split to ~2^-23, B single fp16)
__device__ void run_mma(uint32_t sm0,
        const h16* __restrict__ Ahi, const h16* __restrict__ Alo, size_t lda,
        const h16* __restrict__ B, size_t ldb,
        int nc, float (&acc)[4][4][4])
{
    const int lane = threadIdx.x & 31, warp = threadIdx.x >> 5;
    const int wr = warp >> 2, wc = warp & 3;
    const int g8 = lane & 7, sel = lane >> 3;

    const uint32_t a_row = (uint32_t)(wr * 64 + (sel & 1) * 8 + g8);
    const uint32_t a_col = (uint32_t)((sel >> 1) * 16);
    const uint32_t b_row = (uint32_t)(wc * 32 + (sel >> 1) * 8 + g8);
    const uint32_t b_col = (uint32_t)((sel & 1) * 16);

    fill_stage(sm0, Ahi, Alo, lda, B, ldb, 0);

    for (int c = 0; c < nc; c++) {
        const uint32_t sb = sm0 + (uint32_t)(c & 1) * STAGE_B;
        if (c + 1 < nc) {
            fill_stage(sm0 + (uint32_t)((c + 1) & 1) * STAGE_B,
                       Ahi, Alo, lda, B, ldb, (c + 1) * 32);
            asm volatile("cp.async.wait_group 1;" ::: "memory");
        } else {
            asm volatile("cp.async.wait_group 0;" ::: "memory");
        }
        __syncthreads();

        #pragma unroll
        for (int ks = 0; ks < 2; ks++) {
            const uint32_t kb = (uint32_t)(ks * 32);
            uint32_t ahi[4][4], alo[4][4];
            #pragma unroll
            for (int mt = 0; mt < 4; mt++) {
                uint32_t ad = sb + (a_row + mt * 16) * LDSB32 + a_col + kb;
                ldmx4(ahi[mt], ad + OFF_AHI);
                ldmx4(alo[mt], ad + OFF_ALO);
            }
            #pragma unroll
            for (int ntp = 0; ntp < 2; ntp++) {
                uint32_t bd = sb + (b_row + ntp * 16) * LDSB32 + b_col + kb;
                uint32_t bb[4];
                ldmx4(bb, bd + OFF_B);
                #pragma unroll
                for (int mt = 0; mt < 4; mt++) {
                    hmma(acc[mt][2*ntp],   ahi[mt], bb[0], bb[1]);
                    hmma(acc[mt][2*ntp+1], ahi[mt], bb[2], bb[3]);
                }
                #pragma unroll
                for (int mt = 0; mt < 4; mt++) {
                    hmma(acc[mt][2*ntp],   alo[mt], bb[0], bb[1]);
                    hmma(acc[mt][2*ntp+1], alo[mt], bb[2], bb[3]);
                }
            }
        }
        __syncthreads();
    }
}

// ---------------- fused conversion kernel ----------------
#define N4_X  (MTOK*HID/4)
#define N4_W  (QKVN*HID/4)
#define N4_OW (HID*HID/4)
__global__ __launch_bounds__(256)
void conv_all(const float* __restrict__ x, const float* __restrict__ w,
              const float* __restrict__ ow)
{
    int i = blockIdx.x * blockDim.x + threadIdx.x;
    if (i < N4_X) {
        float4 v = ((const float4*)x)[i];
        uint32_t h0, l0, h1, l1;
        split2(make_float2(v.x, v.y), h0, l0);
        split2(make_float2(v.z, v.w), h1, l1);
        *(uint2*)(g_xhi + (size_t)i * 4) = make_uint2(h0, h1);
        *(uint2*)(g_xlo + (size_t)i * 4) = make_uint2(l0, l1);
    } else if (i < N4_X + N4_W) {
        int j = i - N4_X;
        float4 v = ((const float4*)w)[j];
        *(uint2*)(g_w + (size_t)j * 4) =
            make_uint2(pack2(make_float2(v.x, v.y)), pack2(make_float2(v.z, v.w)));
    } else if (i < N4_X + N4_W + N4_OW) {
        int j = i - N4_X - N4_W;
        float4 v = ((const float4*)ow)[j];
        *(uint2*)(g_ow + (size_t)j * 4) =
            make_uint2(pack2(make_float2(v.x, v.y)), pack2(make_float2(v.z, v.w)));
    }
}

// ---------------- GEMM 1: QKV projection, RoPE+split fused in epilogue ----------------
__global__ __launch_bounds__(256, 2)
void gemm_qkv_tc(const float* __restrict__ bias)
{
    extern __shared__ uint8_t dsm[];
    uint32_t sm0 = s2u(dsm);
    const int bm = blockIdx.y * 128, bn = blockIdx.x * 128;
    float acc[4][4][4] = {};
    run_mma(sm0, g_xhi + (size_t)bm * HID, g_xlo + (size_t)bm * HID, HID,
                 g_w + (size_t)bn * HID, HID, HID/32, acc);
    const int lane = threadIdx.x & 31, warp = threadIdx.x >> 5;
    const int wr = warp >> 2, wc = warp & 3;
    const int g = lane >> 2, i2 = (lane & 3) * 2;
    const int which = bn >> 11;                 // 0=q,1=k,2=v

    if (which < 2) {
        #pragma unroll
        for (int mt = 0; mt < 4; mt++)
        #pragma unroll
        for (int nt = 0; nt < 4; nt++) {
            int r0 = bm + wr*64 + mt*16 + g;
            int cc = bn + wc*32 + nt*8 + i2;
            int within = cc & 2047;
            int h = within >> 7, d = within & 127;
            int j0 = d & 63;
            float f0 = exp2f(-(float)j0 * ROPE_C);
            float f1 = exp2f(-(float)(j0 + 1) * ROPE_C);
            float b0v = bias[cc], b1v = bias[cc+1];
            #pragma unroll
            for (int half = 0; half < 2; half++) {
                int r = r0 + half * 8;
                int b = r >> 11, s = r & (SEQ - 1);
                float x0 = acc[mt][nt][half*2+0] + b0v;
                float x1 = acc[mt][nt][half*2+1] + b1v;
                float c0, s0, c1, s1;
                sincosf((float)s * f0, &s0, &c0);
                sincosf((float)s * f1, &s1, &c1);
                float y0 = x0 * c0 - x1 * s0;
                float y1 = x1 * c1 + x0 * s1;
                int z = b * NHEAD + h;
                size_t o = ((size_t)z * SEQ + s) * HD + d;
                if (which == 0) {
                    uint32_t hh, ll;
                    split2(make_float2(y0, y1), hh, ll);
                    *(uint32_t*)(g_qhi + o) = hh;
                    *(uint32_t*)(g_qlo + o) = ll;
                } else {
                    *(uint32_t*)(g_k + o) = pack2(make_float2(y0, y1));
                }
            }
        }
    } else {
        #pragma unroll
        for (int mt = 0; mt < 4; mt++)
        #pragma unroll
        for (int nt = 0; nt < 4; nt++) {
            int r0 = bm + wr*64 + mt*16 + g;
            int cc = bn + wc*32 + nt*8 + i2;
            float2 v0 = make_float2(acc[mt][nt][0] + bias[cc], acc[mt][nt][1] + bias[cc+1]);
            float2 v1 = make_float2(acc[mt][nt][2] + bias[cc], acc[mt][nt][3] + bias[cc+1]);
            *(float2*)(g_qkv + (size_t)r0 * QKVN + cc)     = v0;
            *(float2*)(g_qkv + (size_t)(r0+8) * QKVN + cc) = v1;
        }
    }
}

// ---------------- V transpose: [s,d] -> [d,s], single fp16 ----------------
__global__ __launch_bounds__(256)
void vtrans()
{
    __shared__ float t[32][33];
    const int z = blockIdx.z, b = z >> 4, h = z & 15;
    const int s0 = blockIdx.x * 32, d0 = blockIdx.y * 32;
    const int tx = threadIdx.x & 31, ty = threadIdx.x >> 5;
    #pragma unroll
    for (int j = 0; j < 4; j++) {
        int s = s0 + ty + j * 8;
        t[ty + j*8][tx] = g_qkv[(size_t)(b * SEQ + s) * QKVN + 2*HID + h * HD + d0 + tx];
    }
    __syncthreads();
    #pragma unroll
    for (int j = 0; j < 4; j++) {
        int d = d0 + ty + j * 8;
        size_t o = ((size_t)z * HD + d) * SEQ + s0 + tx;
        g_vt[o] = __float2half_rn(t[tx][ty + j*8]);
    }
}

// ---------------- GEMM 2: scores — compact lower-tri grid ----------------
__global__ __launch_bounds__(256, 2)
void gemm_scores_tc(const int* __restrict__ amask)
{
    extern __shared__ uint8_t dsm[];
    uint32_t sm0 = s2u(dsm);
    const int t = blockIdx.x;
    int bmt = (int)((sqrtf(8.0f * (float)t + 1.0f) - 1.0f) * 0.5f);
    while ((bmt + 1) * (bmt + 2) / 2 <= t) bmt++;
    while (bmt * (bmt + 1) / 2 > t) bmt--;
    const int bnt = t - bmt * (bmt + 1) / 2;
    const int z = blockIdx.y, b = z >> 4;
    const int bm = bmt * 128, bn = bnt * 128;

    float acc[4][4][4] = {};
    run_mma(sm0, g_qhi + ((size_t)z * SEQ + bm) * HD, g_qlo + ((size_t)z * SEQ + bm) * HD, HD,
                 g_k + ((size_t)z * SEQ + bn) * HD, HD, HD/32, acc);
    const int lane = threadIdx.x & 31, warp = threadIdx.x >> 5;
    const int wr = warp >> 2, wc = warp & 3;
    const int g = lane >> 2, i2 = (lane & 3) * 2;
    const int* am = amask + b * SEQ;
    #pragma unroll
    for (int mt = 0; mt < 4; mt++)
    #pragma unroll
    for (int nt = 0; nt < 4; nt++) {
        int r0 = bm + wr*64 + mt*16 + g;
        int cc = bn + wc*32 + nt*8 + i2;
        float m0 = (am[cc]   != 0) ? 1.f : 0.f;
        float m1 = (am[cc+1] != 0) ? 1.f : 0.f;
        #pragma unroll
        for (int half = 0; half < 2; half++) {
            int r = r0 + half * 8;
            float v0 = acc[mt][nt][half*2+0] * SM_SCALE;
            float v1 = acc[mt][nt][half*2+1] * SM_SCALE;
            if (cc   > r || m0 == 0.f) v0 = NEG_BIG;
            if (cc+1 > r || m1 == 0.f) v1 = NEG_BIG;
            *(float2*)(g_scores + ((size_t)z * SEQ + r) * SEQ + cc) = make_float2(v0, v1);
        }
    }
}

// ---------------- softmax over causal prefix + P split (fp16) ----------------
__global__ __launch_bounds__(256)
void softmax_pconv()
{
    const int bi = blockIdx.x;
    const int r = bi & (SEQ - 1);
    const int z = bi >> 11;
    const int ncols = ((r >> 7) + 1) << 7;
    const size_t rowbase = ((size_t)z * SEQ + r) * SEQ;
    const float* p = g_scores + rowbase;
    const int tid = threadIdx.x;
    __shared__ float red[256];

    const bool act = tid * 8 < ncols;
    float v[8];
    float mx = NEG_BIG;
    if (act) {
        float4 u0 = *(const float4*)(p + tid*8);
        float4 u1 = *(const float4*)(p + tid*8 + 4);
        v[0]=u0.x; v[1]=u0.y; v[2]=u0.z; v[3]=u0.w;
        v[4]=u1.x; v[5]=u1.y; v[6]=u1.z; v[7]=u1.w;
        #pragma unroll
        for (int i = 0; i < 8; i++) mx = fmaxf(mx, v[i]);
    }
    red[tid] = mx; __syncthreads();
    for (int off = 128; off > 0; off >>= 1) {
        if (tid < off) red[tid] = fmaxf(red[tid], red[tid + off]);
        __syncthreads();
    }
    mx = red[0]; __syncthreads();

    float sum = 0.f;
    if (act) {
        #pragma unroll
        for (int i = 0; i < 8; i++) { v[i] = expf(v[i] - mx); sum += v[i]; }
    }
    red[tid] = sum; __syncthreads();
    for (int off = 128; off > 0; off >>= 1) {
        if (tid < off) red[tid] += red[tid + off];
        __syncthreads();
    }
    float inv = 1.0f / red[0];

    if (act) {
        h16* ph = g_phi + rowbase + tid*8;
        h16* pl = g_plo + rowbase + tid*8;
        #pragma unroll
        for (int i = 0; i < 8; i += 2) {
            uint32_t hh, ll;
            split2(make_float2(v[i]*inv, v[i+1]*inv), hh, ll);
            *(uint32_t*)(ph + i) = hh;
            *(uint32_t*)(pl + i) = ll;
        }
    }
}

// ---------------- GEMM 3: attn = P @ V, LPT order ----------------
__global__ __launch_bounds__(256, 2)
void gemm_pv_tc()
{
    extern __shared__ uint8_t dsm[];
    uint32_t sm0 = s2u(dsm);
    const int z = blockIdx.y, b = z >> 4, h = z & 15;
    const int bm = (gridDim.x - 1 - blockIdx.x) * 128;
    const int nc = (bm + 128) / 32;
    float acc[4][4][4] = {};
    run_mma(sm0, g_phi + ((size_t)z * SEQ + bm) * SEQ, g_plo + ((size_t)z * SEQ + bm) * SEQ, SEQ,
                 g_vt + (size_t)z * HD * SEQ, SEQ, nc, acc);
    const int lane = threadIdx.x & 31, warp = threadIdx.x >> 5;
    const int wr = warp >> 2, wc = warp & 3;
    const int g = lane >> 2, i2 = (lane & 3) * 2;
    #pragma unroll
    for (int mt = 0; mt < 4; mt++)
    #pragma unroll
    for (int nt = 0; nt < 4; nt++) {
        int r0 = bm + wr*64 + mt*16 + g;
        int cc = wc*32 + nt*8 + i2;
        #pragma unroll
        for (int half = 0; half < 2; half++) {
            int r = r0 + half * 8;
            size_t o = (size_t)(b * SEQ + r) * HID + h * HD + cc;
            uint32_t hh, ll;
            split2(make_float2(acc[mt][nt][half*2+0], acc[mt][nt][half*2+1]), hh, ll);
            *(uint32_t*)(g_ahi + o) = hh;
            *(uint32_t*)(g_alo + o) = ll;
        }
    }
}

// ---------------- GEMM 4: out = attn @ out_w^T + out_b ----------------
__global__ __launch_bounds__(256, 2)
void gemm_out_tc(const float* __restrict__ bias, float* __restrict__ outp)
{
    extern __shared__ uint8_t dsm[];
    uint32_t sm0 = s2u(dsm);
    const int bm = blockIdx.y * 128, bn = blockIdx.x * 128;
    float acc[4][4][4] = {};
    run_mma(sm0, g_ahi + (size_t)bm * HID, g_alo + (size_t)bm * HID, HID,
                 g_ow + (size_t)bn * HID, HID, HID/32, acc);
    const int lane = threadIdx.x & 31, warp = threadIdx.x >> 5;
    const int wr = warp >> 2, wc = warp & 3;
    const int g = lane >> 2, i2 = (lane & 3) * 2;
    #pragma unroll
    for (int mt = 0; mt < 4; mt++)
    #pragma unroll
    for (int nt = 0; nt < 4; nt++) {
        int r0 = bm + wr*64 + mt*16 + g;
        int cc = bn + wc*32 + nt*8 + i2;
        float2 v0 = make_float2(acc[mt][nt][0] + bias[cc], acc[mt][nt][1] + bias[cc+1]);
        float2 v1 = make_float2(acc[mt][nt][2] + bias[cc], acc[mt][nt][3] + bias[cc+1]);
        *(float2*)(outp + (size_t)r0 * HID + cc)     = v0;
        *(float2*)(outp + (size_t)(r0+8) * HID + cc) = v1;
    }
}

// ---------------------------------------------------------------------------
extern "C" void kernel_launch(void* const* d_in, const int* in_sizes, int n_in,
                              void* d_out, int out_size)
{
    (void)in_sizes; (void)n_in; (void)out_size;
    const int*   amask = (const int*)  d_in[1];
    const float* qkv_b = (const float*)d_in[3];
    const float* out_b = (const float*)d_in[5];
    float* outp = (float*)d_out;

    cudaFuncSetAttribute(gemm_qkv_tc,    cudaFuncAttributeMaxDynamicSharedMemorySize, DYN_SMEM);
    cudaFuncSetAttribute(gemm_scores_tc, cudaFuncAttributeMaxDynamicSharedMemorySize, DYN_SMEM);
    cudaFuncSetAttribute(gemm_pv_tc,     cudaFuncAttributeMaxDynamicSharedMemorySize, DYN_SMEM);
    cudaFuncSetAttribute(gemm_out_tc,    cudaFuncAttributeMaxDynamicSharedMemorySize, DYN_SMEM);

    const int conv_blocks = (N4_X + N4_W + N4_OW + 255) / 256;
    conv_all<<<conv_blocks, 256>>>((const float*)d_in[0], (const float*)d_in[2],
                                   (const float*)d_in[4]);
    gemm_qkv_tc   <<<dim3(QKVN/128, MTOK/128), 256, DYN_SMEM>>>(qkv_b);
    vtrans        <<<dim3(SEQ/32, HD/32, NBH), 256>>>();
    gemm_scores_tc<<<dim3(136, NBH), 256, DYN_SMEM>>>(amask);
    softmax_pconv <<<NBH*SEQ, 256>>>();
    gemm_pv_tc    <<<dim3(SEQ/128, NBH), 256, DYN_SMEM>>>();
    gemm_out_tc   <<<dim3(HID/128, MTOK/128), 256, DYN_SMEM>>>(out_b, outp);
}